// round 5
// baseline (speedup 1.0000x reference)
#include <cuda_runtime.h>
#include <cuda_bf16.h>
#include <math.h>

typedef unsigned int u32;

// Problem constants
constexpr int BB = 2, RR = 64, CC = 2048, EE = 128, HH = 4, DH = 32;
constexpr long long MROWS = (long long)BB * RR * CC;        // 262144
constexpr long long QKV_ELEMS = MROWS * EE;                  // 33,554,432
constexpr int NTILES = (int)(MROWS / 64);                    // 4096
constexpr int NKV = BB * RR * HH;                            // 512

// Scratch (device globals — no runtime allocation)
__device__ float g_q[QKV_ELEMS];
__device__ float g_k[QKV_ELEMS];
__device__ float g_v[QKV_ELEMS];
__device__ float g_ktv_part[NKV * 4 * DH * DH];              // 8 MB (4 partials)
__device__ float g_ksum_part[NKV * 4 * DH];                  // 256 KB
// Pre-swizzled bf16 weight images: [matrix 0..3][hi 2048 | lo 2048] uint4 chunks
__device__ uint4 g_wimg[4 * 4096];

// ---------------------------------------------------------------------------
// helpers
// ---------------------------------------------------------------------------
__device__ __forceinline__ void ldsm4(u32 a, u32& r0, u32& r1, u32& r2, u32& r3) {
    asm volatile("ldmatrix.sync.aligned.m8n8.x4.shared.b16 {%0,%1,%2,%3},[%4];"
                 : "=r"(r0), "=r"(r1), "=r"(r2), "=r"(r3) : "r"(a));
}
__device__ __forceinline__ void ldsm4t(u32 a, u32& r0, u32& r1, u32& r2, u32& r3) {
    asm volatile("ldmatrix.sync.aligned.m8n8.x4.trans.shared.b16 {%0,%1,%2,%3},[%4];"
                 : "=r"(r0), "=r"(r1), "=r"(r2), "=r"(r3) : "r"(a));
}
__device__ __forceinline__ void mma_bf16(float c[4], u32 a0, u32 a1,
                                         u32 a2, u32 a3, u32 b0, u32 b1) {
    asm volatile(
        "mma.sync.aligned.m16n8k16.row.col.f32.bf16.bf16.f32 "
        "{%0,%1,%2,%3},{%4,%5,%6,%7},{%8,%9},{%0,%1,%2,%3};"
        : "+f"(c[0]), "+f"(c[1]), "+f"(c[2]), "+f"(c[3])
        : "r"(a0), "r"(a1), "r"(a2), "r"(a3), "r"(b0), "r"(b1));
}

// Convert 8 consecutive floats to hi/lo bf16 packed as uint4 each.
__device__ __forceinline__ void cvt8(const float* f, uint4& hi, uint4& lo) {
    u32 h[4];
    u32 l[4];
#pragma unroll
    for (int i = 0; i < 4; ++i) {
        float a = f[2 * i];
        float b = f[2 * i + 1];
        __nv_bfloat16 ah16 = __float2bfloat16_rn(a);
        __nv_bfloat16 bh16 = __float2bfloat16_rn(b);
        float ar = a - __bfloat162float(ah16);
        float br = b - __bfloat162float(bh16);
        __nv_bfloat162 hp = __halves2bfloat162(ah16, bh16);
        __nv_bfloat162 lp = __floats2bfloat162_rn(ar, br);
        h[i] = *(u32*)&hp;
        l[i] = *(u32*)&lp;
    }
    hi = make_uint4(h[0], h[1], h[2], h[3]);
    lo = make_uint4(l[0], l[1], l[2], l[3]);
}

__device__ __forceinline__ float elu1(float x) {
    return (x > 0.f) ? (x + 1.f) : expf(x);
}

// smem layout (bytes) for GEMM kernels: Ahi[0,16K) Alo[16K,32K) Whi[32K,64K) Wlo[64K,96K)
constexpr int SOFF_AHI = 0;
constexpr int SOFF_ALO = 16384;
constexpr int SOFF_WHI = 32768;
constexpr int SOFF_WLO = 65536;
constexpr int SMEM_GEMM = 98304;
// tout extras: q staging overlaps W region during phase 1; KtV + ksum after W.
constexpr int SOFF_QSTAGE = 32768;                    // 64 rows * 132 floats = 33792 B
constexpr int SOFF_KTV = 98304;                       // 4 * 1032 floats = 16512 B
constexpr int SOFF_KSUM = 98304 + 16512;              // 512 B
constexpr int SMEM_TOUT = SOFF_KSUM + 512;            // 115328 B

// ---------------------------------------------------------------------------
// Kernel 0: precompute bf16 hi/lo swizzled images of the 4 weight matrices.
// ---------------------------------------------------------------------------
__global__ __launch_bounds__(256)
void prep_w_kernel(const float* __restrict__ Wq, const float* __restrict__ Wk,
                   const float* __restrict__ Wv, const float* __restrict__ Wo)
{
    const float* Ws[4] = {Wq, Wk, Wv, Wo};
    const float4* W = (const float4*)Ws[blockIdx.x];
    uint4* dst = g_wimg + blockIdx.x * 4096;
    const int tid = threadIdx.x;
#pragma unroll
    for (int it = 0; it < 8; ++it) {
        int idx = tid + it * 256;            // 2048 chunks
        int row = idx >> 4;
        int ch = idx & 15;
        float4 f0 = W[row * 32 + ch * 2];
        float4 f1 = W[row * 32 + ch * 2 + 1];
        float f[8] = {f0.x, f0.y, f0.z, f0.w, f1.x, f1.y, f1.z, f1.w};
        uint4 hi, lo;
        cvt8(f, hi, lo);
        int c = row * 16 + (ch ^ (row & 7));
        dst[c] = hi;
        dst[2048 + c] = lo;
    }
}

// ---------------------------------------------------------------------------
// Kernel 1: fused QKV projection via bf16 hi/lo tensor-core mma (3-term split).
// ---------------------------------------------------------------------------
__global__ __launch_bounds__(256, 2)
void qkv_mma_kernel(const float* __restrict__ X,
                    const float* __restrict__ bq,
                    const float* __restrict__ bk,
                    const float* __restrict__ bv)
{
    extern __shared__ char smem[];
    const u32 sb = (u32)__cvta_generic_to_shared(smem);

    const int tid = threadIdx.x;
    const int lane = tid & 31;
    const int w = tid >> 5;
    const long long m0 = (long long)blockIdx.x * 64;

    // ---- Load + convert X tile (64x128 f32 -> bf16 hi/lo, swizzled) ----
    {
        const float4* Xg = (const float4*)(X + m0 * EE);
#pragma unroll
        for (int it = 0; it < 4; ++it) {
            int idx = tid + it * 256;            // 1024 chunks (row, ch)
            int row = idx >> 4;
            int ch = idx & 15;
            float4 f0 = Xg[row * 32 + ch * 2];
            float4 f1 = Xg[row * 32 + ch * 2 + 1];
            float f[8] = {f0.x, f0.y, f0.z, f0.w, f1.x, f1.y, f1.z, f1.w};
            uint4 hi, lo;
            cvt8(f, hi, lo);
            int off = row * 256 + ((ch ^ (row & 7)) << 4);
            *(uint4*)(smem + SOFF_AHI + off) = hi;
            *(uint4*)(smem + SOFF_ALO + off) = lo;
        }
    }

    const int wr0 = (w & 1) * 32;
    const int wc0 = (w >> 1) * 32;
    const int quad = lane >> 3;
    const int l7 = lane & 7;
    const int arow0 = wr0 + l7 + (quad & 1) * 8;
    const int arow1 = arow0 + 16;
    const int axor0 = arow0 & 7;
    const int axor1 = arow1 & 7;
    const int ac_off = quad >> 1;
    const int krow_base = l7 + (quad & 1) * 8;
    const int bxor = krow_base & 7;
    const int g = lane >> 2;
    const int t2 = lane & 3;

    const float* blist[3] = {bq, bk, bv};

#pragma unroll 1
    for (int j = 0; j < 3; ++j) {
        __syncthreads();
        {
            const uint4* src = g_wimg + j * 4096;
#pragma unroll
            for (int it = 0; it < 8; ++it) {
                int i = tid + it * 256;
                *(uint4*)(smem + SOFF_WHI + i * 16) = src[i];
                *(uint4*)(smem + SOFF_WLO + i * 16) = src[2048 + i];
            }
        }
        __syncthreads();

        float acc[2][4][4];
#pragma unroll
        for (int ii = 0; ii < 2; ++ii)
#pragma unroll
            for (int jj = 0; jj < 4; ++jj)
#pragma unroll
                for (int kk = 0; kk < 4; ++kk) acc[ii][jj][kk] = 0.f;

#pragma unroll 1
        for (int ks = 0; ks < 8; ++ks) {
            u32 ah0[4], ah1[4], al0[4], al1[4];
            {
                int offA0 = arow0 * 256 + (((ks * 2 + ac_off) ^ axor0) << 4);
                int offA1 = arow1 * 256 + (((ks * 2 + ac_off) ^ axor1) << 4);
                ldsm4(sb + SOFF_AHI + offA0, ah0[0], ah0[1], ah0[2], ah0[3]);
                ldsm4(sb + SOFF_ALO + offA0, al0[0], al0[1], al0[2], al0[3]);
                ldsm4(sb + SOFF_AHI + offA1, ah1[0], ah1[1], ah1[2], ah1[3]);
                ldsm4(sb + SOFF_ALO + offA1, al1[0], al1[1], al1[2], al1[3]);
            }
#pragma unroll
            for (int p = 0; p < 2; ++p) {
                int chB = (wc0 >> 3) + p * 2 + (quad >> 1);
                int offB = (ks * 16 + krow_base) * 256 + ((chB ^ bxor) << 4);
                u32 wb0, wb1, wb2, wb3;
                ldsm4t(sb + SOFF_WHI + offB, wb0, wb1, wb2, wb3);
                mma_bf16(acc[0][2 * p],     ah0[0], ah0[1], ah0[2], ah0[3], wb0, wb1);
                mma_bf16(acc[0][2 * p + 1], ah0[0], ah0[1], ah0[2], ah0[3], wb2, wb3);
                mma_bf16(acc[1][2 * p],     ah1[0], ah1[1], ah1[2], ah1[3], wb0, wb1);
                mma_bf16(acc[1][2 * p + 1], ah1[0], ah1[1], ah1[2], ah1[3], wb2, wb3);
                mma_bf16(acc[0][2 * p],     al0[0], al0[1], al0[2], al0[3], wb0, wb1);
                mma_bf16(acc[0][2 * p + 1], al0[0], al0[1], al0[2], al0[3], wb2, wb3);
                mma_bf16(acc[1][2 * p],     al1[0], al1[1], al1[2], al1[3], wb0, wb1);
                mma_bf16(acc[1][2 * p + 1], al1[0], al1[1], al1[2], al1[3], wb2, wb3);
                ldsm4t(sb + SOFF_WLO + offB, wb0, wb1, wb2, wb3);
                mma_bf16(acc[0][2 * p],     ah0[0], ah0[1], ah0[2], ah0[3], wb0, wb1);
                mma_bf16(acc[0][2 * p + 1], ah0[0], ah0[1], ah0[2], ah0[3], wb2, wb3);
                mma_bf16(acc[1][2 * p],     ah1[0], ah1[1], ah1[2], ah1[3], wb0, wb1);
                mma_bf16(acc[1][2 * p + 1], ah1[0], ah1[1], ah1[2], ah1[3], wb2, wb3);
            }
        }

        float* outp = (j == 0) ? g_q : (j == 1) ? g_k : g_v;
        const float* bias = blist[j];
        const bool act = (j < 2);
#pragma unroll
        for (int mt = 0; mt < 2; ++mt) {
#pragma unroll
            for (int nt = 0; nt < 4; ++nt) {
                int col = wc0 + nt * 8 + t2 * 2;
                float2 bb = *(const float2*)(bias + col);
                long long r0g = m0 + wr0 + mt * 16 + g;
                float v0 = acc[mt][nt][0] + bb.x;
                float v1 = acc[mt][nt][1] + bb.y;
                float v2 = acc[mt][nt][2] + bb.x;
                float v3 = acc[mt][nt][3] + bb.y;
                if (act) { v0 = elu1(v0); v1 = elu1(v1); v2 = elu1(v2); v3 = elu1(v3); }
                *(float2*)(outp + r0g * EE + col)       = make_float2(v0, v1);
                *(float2*)(outp + (r0g + 8) * EE + col) = make_float2(v2, v3);
            }
        }
    }
}

// ---------------------------------------------------------------------------
// Kernel 2: partial KtV/ksum. grid = NKV*4; block bx: blk = bx>>2 (br*4+h),
// part = bx&3 covers cols [part*512, part*512+512).
// ---------------------------------------------------------------------------
__global__ __launch_bounds__(256)
void ktv_kernel()
{
    __shared__ float sk[64][32];
    __shared__ float sv[64][32];

    const int bx = blockIdx.x;
    const int part = bx & 3;
    const int blk = bx >> 2;              // br*H + h
    const int h = blk & 3;
    const int br = blk >> 2;
    const long long base = (long long)br * CC * EE + h * DH;

    const int tid = threadIdx.x;
    const int d = tid & 31;
    const int eg = tid >> 5;

    float a0 = 0.f, a1 = 0.f, a2 = 0.f, a3 = 0.f, ks = 0.f;

    const int cbeg = part * 512;
    for (int c0 = cbeg; c0 < cbeg + 512; c0 += 64) {
        __syncthreads();
        #pragma unroll
        for (int it = 0; it < 8; ++it) {
            int idx = tid + it * 256;
            int r = idx >> 5;
            int c = idx & 31;
            long long gi = base + (long long)(c0 + r) * EE + c;
            sk[r][c] = g_k[gi];
            sv[r][c] = g_v[gi];
        }
        __syncthreads();
        #pragma unroll 8
        for (int cc = 0; cc < 64; ++cc) {
            float kd = sk[cc][d];
            float4 ve = *(const float4*)&sv[cc][eg * 4];
            a0 = fmaf(kd, ve.x, a0);
            a1 = fmaf(kd, ve.y, a1);
            a2 = fmaf(kd, ve.z, a2);
            a3 = fmaf(kd, ve.w, a3);
            ks += kd;
        }
    }

    float* ktv = g_ktv_part + (long long)bx * DH * DH;
    float4 o = {a0, a1, a2, a3};
    *(float4*)&ktv[d * 32 + eg * 4] = o;
    if (eg == 0) g_ksum_part[bx * 32 + d] = ks;
}

// ---------------------------------------------------------------------------
// Kernel 3: fused t + output projection.
// Per 64-row tile: stage q, reduce KtV partials, compute Z and t in regs,
// write t as swizzled bf16 hi/lo into A buffers, then mma with Wo.
// ---------------------------------------------------------------------------
__global__ __launch_bounds__(256, 2)
void tout_kernel(const float* __restrict__ bo, float* __restrict__ out)
{
    extern __shared__ char smem[];
    const u32 sb = (u32)__cvta_generic_to_shared(smem);
    float* sq = (float*)(smem + SOFF_QSTAGE);        // [64][132] floats
    float* sKtV = (float*)(smem + SOFF_KTV);         // [4][1032] (32x32 + pad 8)
    float* sKsum = (float*)(smem + SOFF_KSUM);       // 128

    const int tid = threadIdx.x;
    const int lane = tid & 31;
    const int w = tid >> 5;
    const long long tile = blockIdx.x;
    const long long m0 = tile * 64;
    const int br = (int)(tile >> 5);                 // (b*R + r)

    // ---- Phase 1: stage q (coalesced), reduce KtV partials + ksum ----
    {
        const float4* Qg = (const float4*)(g_q + m0 * EE);
#pragma unroll
        for (int it = 0; it < 8; ++it) {
            int idx = tid + it * 256;                // 2048 float4
            int row = idx >> 5;
            int c4 = idx & 31;
            *(float4*)(sq + row * 132 + c4 * 4) = Qg[idx];
        }
        const float4* Kp = (const float4*)g_ktv_part;
#pragma unroll
        for (int it = 0; it < 4; ++it) {
            int i = tid + it * 256;                  // 1024 float4 positions
            int h = i >> 8;
            int rest = i & 255;
            long long b0 = (long long)((br * 4 + h) * 4) * 256 + rest;
            float4 p0 = Kp[b0];
            float4 p1 = Kp[b0 + 256];
            float4 p2 = Kp[b0 + 512];
            float4 p3 = Kp[b0 + 768];
            float4 s;
            s.x = (p0.x + p1.x) + (p2.x + p3.x);
            s.y = (p0.y + p1.y) + (p2.y + p3.y);
            s.z = (p0.z + p1.z) + (p2.z + p3.z);
            s.w = (p0.w + p1.w) + (p2.w + p3.w);
            *(float4*)(sKtV + h * 1032 + rest * 4) = s;
        }
        if (tid < 128) {
            int h = tid >> 5;
            int d = tid & 31;
            int b0 = ((br * 4 + h) * 4) * 32 + d;
            sKsum[tid] = (g_ksum_part[b0] + g_ksum_part[b0 + 32]) +
                         (g_ksum_part[b0 + 64] + g_ksum_part[b0 + 96]);
        }
    }
    __syncthreads();

    // ---- Phase 2: per-(row,head) compute Z and t[32], write bf16 images ----
    {
        const int row = tid >> 2;
        const int h = tid & 3;
        float qv[32];
        const float* qrow = sq + row * 132 + h * 32;
#pragma unroll
        for (int i = 0; i < 8; ++i) {
            float4 f = *(const float4*)(qrow + i * 4);
            qv[4 * i] = f.x; qv[4 * i + 1] = f.y; qv[4 * i + 2] = f.z; qv[4 * i + 3] = f.w;
        }
        float z = 0.f;
        const float* ksrow = sKsum + h * 32;
#pragma unroll
        for (int d = 0; d < 32; ++d) z = fmaf(qv[d], ksrow[d], z);
        z = 1.0f / (z + 1e-6f);

        float t[32];
#pragma unroll
        for (int e = 0; e < 32; ++e) t[e] = 0.f;
        const float* kt = sKtV + h * 1032;
#pragma unroll
        for (int d = 0; d < 32; ++d) {
            float qd = qv[d];
#pragma unroll
            for (int j = 0; j < 8; ++j) {
                float4 kr = *(const float4*)(kt + d * 32 + j * 4);
                t[4 * j]     = fmaf(qd, kr.x, t[4 * j]);
                t[4 * j + 1] = fmaf(qd, kr.y, t[4 * j + 1]);
                t[4 * j + 2] = fmaf(qd, kr.z, t[4 * j + 2]);
                t[4 * j + 3] = fmaf(qd, kr.w, t[4 * j + 3]);
            }
        }
#pragma unroll
        for (int e = 0; e < 32; ++e) t[e] *= z;

        // write 4 hi/lo uint4 chunks: cols h*32.. in swizzled A image
#pragma unroll
        for (int j = 0; j < 4; ++j) {
            uint4 hi, lo;
            cvt8(t + j * 8, hi, lo);
            int ch = h * 4 + j;
            int off = row * 256 + ((ch ^ (row & 7)) << 4);
            *(uint4*)(smem + SOFF_AHI + off) = hi;
            *(uint4*)(smem + SOFF_ALO + off) = lo;
        }
    }
    __syncthreads();   // q staging reads done; A images complete

    // ---- Phase 3: copy Wo images (overwrites q staging), then mma ----
    {
        const uint4* wsrc = g_wimg + 3 * 4096;
#pragma unroll
        for (int it = 0; it < 8; ++it) {
            int i = tid + it * 256;
            *(uint4*)(smem + SOFF_WHI + i * 16) = wsrc[i];
            *(uint4*)(smem + SOFF_WLO + i * 16) = wsrc[2048 + i];
        }
    }
    __syncthreads();

    const int wr0 = (w & 1) * 32;
    const int wc0 = (w >> 1) * 32;
    const int quad = lane >> 3;
    const int l7 = lane & 7;
    const int arow0 = wr0 + l7 + (quad & 1) * 8;
    const int arow1 = arow0 + 16;
    const int axor0 = arow0 & 7;
    const int axor1 = arow1 & 7;
    const int ac_off = quad >> 1;
    const int krow_base = l7 + (quad & 1) * 8;
    const int bxor = krow_base & 7;
    const int g = lane >> 2;
    const int t2 = lane & 3;

    float acc[2][4][4];
#pragma unroll
    for (int ii = 0; ii < 2; ++ii)
#pragma unroll
        for (int jj = 0; jj < 4; ++jj)
#pragma unroll
            for (int kk = 0; kk < 4; ++kk) acc[ii][jj][kk] = 0.f;

#pragma unroll 1
    for (int ks = 0; ks < 8; ++ks) {
        u32 ah0[4], ah1[4], al0[4], al1[4];
        {
            int offA0 = arow0 * 256 + (((ks * 2 + ac_off) ^ axor0) << 4);
            int offA1 = arow1 * 256 + (((ks * 2 + ac_off) ^ axor1) << 4);
            ldsm4(sb + SOFF_AHI + offA0, ah0[0], ah0[1], ah0[2], ah0[3]);
            ldsm4(sb + SOFF_ALO + offA0, al0[0], al0[1], al0[2], al0[3]);
            ldsm4(sb + SOFF_AHI + offA1, ah1[0], ah1[1], ah1[2], ah1[3]);
            ldsm4(sb + SOFF_ALO + offA1, al1[0], al1[1], al1[2], al1[3]);
        }
#pragma unroll
        for (int p = 0; p < 2; ++p) {
            int chB = (wc0 >> 3) + p * 2 + (quad >> 1);
            int offB = (ks * 16 + krow_base) * 256 + ((chB ^ bxor) << 4);
            u32 wb0, wb1, wb2, wb3;
            ldsm4t(sb + SOFF_WHI + offB, wb0, wb1, wb2, wb3);
            mma_bf16(acc[0][2 * p],     ah0[0], ah0[1], ah0[2], ah0[3], wb0, wb1);
            mma_bf16(acc[0][2 * p + 1], ah0[0], ah0[1], ah0[2], ah0[3], wb2, wb3);
            mma_bf16(acc[1][2 * p],     ah1[0], ah1[1], ah1[2], ah1[3], wb0, wb1);
            mma_bf16(acc[1][2 * p + 1], ah1[0], ah1[1], ah1[2], ah1[3], wb2, wb3);
            mma_bf16(acc[0][2 * p],     al0[0], al0[1], al0[2], al0[3], wb0, wb1);
            mma_bf16(acc[0][2 * p + 1], al0[0], al0[1], al0[2], al0[3], wb2, wb3);
            mma_bf16(acc[1][2 * p],     al1[0], al1[1], al1[2], al1[3], wb0, wb1);
            mma_bf16(acc[1][2 * p + 1], al1[0], al1[1], al1[2], al1[3], wb2, wb3);
            ldsm4t(sb + SOFF_WLO + offB, wb0, wb1, wb2, wb3);
            mma_bf16(acc[0][2 * p],     ah0[0], ah0[1], ah0[2], ah0[3], wb0, wb1);
            mma_bf16(acc[0][2 * p + 1], ah0[0], ah0[1], ah0[2], ah0[3], wb2, wb3);
            mma_bf16(acc[1][2 * p],     ah1[0], ah1[1], ah1[2], ah1[3], wb0, wb1);
            mma_bf16(acc[1][2 * p + 1], ah1[0], ah1[1], ah1[2], ah1[3], wb2, wb3);
        }
    }

#pragma unroll
    for (int mt = 0; mt < 2; ++mt) {
#pragma unroll
        for (int nt = 0; nt < 4; ++nt) {
            int col = wc0 + nt * 8 + t2 * 2;
            float2 bb = *(const float2*)(bo + col);
            long long r0g = m0 + wr0 + mt * 16 + g;
            float v0 = acc[mt][nt][0] + bb.x;
            float v1 = acc[mt][nt][1] + bb.y;
            float v2 = acc[mt][nt][2] + bb.x;
            float v3 = acc[mt][nt][3] + bb.y;
            *(float2*)(out + r0g * EE + col)       = make_float2(v0, v1);
            *(float2*)(out + (r0g + 8) * EE + col) = make_float2(v2, v3);
        }
    }
}

// ---------------------------------------------------------------------------
extern "C" void kernel_launch(void* const* d_in, const int* in_sizes, int n_in,
                              void* d_out, int out_size)
{
    const float* X  = (const float*)d_in[0];
    const float* Wq = (const float*)d_in[1];
    const float* bq = (const float*)d_in[2];
    const float* Wk = (const float*)d_in[3];
    const float* bk = (const float*)d_in[4];
    const float* Wv = (const float*)d_in[5];
    const float* bv = (const float*)d_in[6];
    const float* Wo = (const float*)d_in[7];
    const float* bo = (const float*)d_in[8];
    float* out = (float*)d_out;

    cudaFuncSetAttribute(qkv_mma_kernel, cudaFuncAttributeMaxDynamicSharedMemorySize, SMEM_GEMM);
    cudaFuncSetAttribute(tout_kernel, cudaFuncAttributeMaxDynamicSharedMemorySize, SMEM_TOUT);

    prep_w_kernel<<<4, 256>>>(Wq, Wk, Wv, Wo);
    qkv_mma_kernel<<<NTILES, 256, SMEM_GEMM>>>(X, bq, bk, bv);
    ktv_kernel<<<NKV * 4, 256>>>();
    tout_kernel<<<NTILES, 256, SMEM_TOUT>>>(bo, out);
}

// round 6
// speedup vs baseline: 1.2107x; 1.2107x over previous
#include <cuda_runtime.h>
#include <cuda_bf16.h>
#include <math.h>

typedef unsigned int u32;

// Problem constants
constexpr int BB = 2, RR = 64, CC = 2048, EE = 128, HH = 4, DH = 32;
constexpr long long MROWS = (long long)BB * RR * CC;        // 262144
constexpr long long QKV_ELEMS = MROWS * EE;                  // 33,554,432
constexpr int NTILES = (int)(MROWS / 64);                    // 4096
constexpr int NKV = BB * RR * HH;                            // 512
constexpr int NBR = BB * RR;                                 // 128

// Scratch (device globals — no runtime allocation)
__device__ float g_q[QKV_ELEMS];
__device__ float g_k[QKV_ELEMS];
__device__ float g_v[QKV_ELEMS];
__device__ float g_ktv_part[NKV * 4 * DH * DH];              // 8 MB (4 partials)
__device__ float g_ksum_part[NKV * 4 * DH];                  // 256 KB
__device__ float g_ksum_final[NKV * DH];                     // 64 KB
// Pre-swizzled bf16 weight images: [matrix 0..3][hi 2048 | lo 2048] uint4 chunks
__device__ uint4 g_wimg[4 * 4096];
// Pre-swizzled bf16 KtV images: per br: [hi 512 | lo 512] uint4 (h,d,cc)
__device__ uint4 g_ktvimg[NBR * 1024];

// ---------------------------------------------------------------------------
// helpers
// ---------------------------------------------------------------------------
__device__ __forceinline__ void ldsm4(u32 a, u32& r0, u32& r1, u32& r2, u32& r3) {
    asm volatile("ldmatrix.sync.aligned.m8n8.x4.shared.b16 {%0,%1,%2,%3},[%4];"
                 : "=r"(r0), "=r"(r1), "=r"(r2), "=r"(r3) : "r"(a));
}
__device__ __forceinline__ void ldsm4t(u32 a, u32& r0, u32& r1, u32& r2, u32& r3) {
    asm volatile("ldmatrix.sync.aligned.m8n8.x4.trans.shared.b16 {%0,%1,%2,%3},[%4];"
                 : "=r"(r0), "=r"(r1), "=r"(r2), "=r"(r3) : "r"(a));
}
__device__ __forceinline__ void mma_bf16(float c[4], u32 a0, u32 a1,
                                         u32 a2, u32 a3, u32 b0, u32 b1) {
    asm volatile(
        "mma.sync.aligned.m16n8k16.row.col.f32.bf16.bf16.f32 "
        "{%0,%1,%2,%3},{%4,%5,%6,%7},{%8,%9},{%0,%1,%2,%3};"
        : "+f"(c[0]), "+f"(c[1]), "+f"(c[2]), "+f"(c[3])
        : "r"(a0), "r"(a1), "r"(a2), "r"(a3), "r"(b0), "r"(b1));
}

__device__ __forceinline__ void cvt2(float a, float b, u32& hi, u32& lo) {
    __nv_bfloat16 ah16 = __float2bfloat16_rn(a);
    __nv_bfloat16 bh16 = __float2bfloat16_rn(b);
    float ar = a - __bfloat162float(ah16);
    float br = b - __bfloat162float(bh16);
    __nv_bfloat162 hp = __halves2bfloat162(ah16, bh16);
    __nv_bfloat162 lp = __floats2bfloat162_rn(ar, br);
    hi = *(u32*)&hp;
    lo = *(u32*)&lp;
}

// Convert 8 consecutive floats to hi/lo bf16 packed as uint4 each.
__device__ __forceinline__ void cvt8(const float* f, uint4& hi, uint4& lo) {
    u32 h[4];
    u32 l[4];
#pragma unroll
    for (int i = 0; i < 4; ++i) cvt2(f[2 * i], f[2 * i + 1], h[i], l[i]);
    hi = make_uint4(h[0], h[1], h[2], h[3]);
    lo = make_uint4(l[0], l[1], l[2], l[3]);
}

__device__ __forceinline__ float elu1(float x) {
    return (x > 0.f) ? (x + 1.f) : expf(x);
}

// smem layout (bytes) for GEMM kernels: Ahi[0,16K) Alo[16K,32K) Whi[32K,64K) Wlo[64K,96K)
constexpr int SOFF_AHI = 0;
constexpr int SOFF_ALO = 16384;
constexpr int SOFF_WHI = 32768;
constexpr int SOFF_WLO = 65536;
constexpr int SMEM_GEMM = 98304;
// tout extras (after the 96KB GEMM area)
constexpr int SOFF_KSUMP = 98304;                 // 16*9 floats padded = 576 B
constexpr int SOFF_ZP    = 98304 + 576;           // 64*16 floats = 4096 B
constexpr int SOFF_Z     = 98304 + 576 + 4096;    // 64*4 floats = 1024 B
constexpr int SMEM_TOUT  = SOFF_Z + 1024;         // 104000 B

// ---------------------------------------------------------------------------
// Kernel 0: precompute bf16 hi/lo swizzled images of the 4 weight matrices.
// ---------------------------------------------------------------------------
__global__ __launch_bounds__(256)
void prep_w_kernel(const float* __restrict__ Wq, const float* __restrict__ Wk,
                   const float* __restrict__ Wv, const float* __restrict__ Wo)
{
    const float* Ws[4] = {Wq, Wk, Wv, Wo};
    const float4* W = (const float4*)Ws[blockIdx.x];
    uint4* dst = g_wimg + blockIdx.x * 4096;
    const int tid = threadIdx.x;
#pragma unroll
    for (int it = 0; it < 8; ++it) {
        int idx = tid + it * 256;            // 2048 chunks
        int row = idx >> 4;
        int ch = idx & 15;
        float4 f0 = W[row * 32 + ch * 2];
        float4 f1 = W[row * 32 + ch * 2 + 1];
        float f[8] = {f0.x, f0.y, f0.z, f0.w, f1.x, f1.y, f1.z, f1.w};
        uint4 hi, lo;
        cvt8(f, hi, lo);
        int c = row * 16 + (ch ^ (row & 7));
        dst[c] = hi;
        dst[2048 + c] = lo;
    }
}

// ---------------------------------------------------------------------------
// Kernel 1: fused QKV projection via bf16 hi/lo tensor-core mma (3-term split).
// ---------------------------------------------------------------------------
__global__ __launch_bounds__(256, 2)
void qkv_mma_kernel(const float* __restrict__ X,
                    const float* __restrict__ bq,
                    const float* __restrict__ bk,
                    const float* __restrict__ bv)
{
    extern __shared__ char smem[];
    const u32 sb = (u32)__cvta_generic_to_shared(smem);

    const int tid = threadIdx.x;
    const int lane = tid & 31;
    const int w = tid >> 5;
    const long long m0 = (long long)blockIdx.x * 64;

    // ---- Load + convert X tile (64x128 f32 -> bf16 hi/lo, swizzled) ----
    {
        const float4* Xg = (const float4*)(X + m0 * EE);
#pragma unroll
        for (int it = 0; it < 4; ++it) {
            int idx = tid + it * 256;            // 1024 chunks (row, ch)
            int row = idx >> 4;
            int ch = idx & 15;
            float4 f0 = Xg[row * 32 + ch * 2];
            float4 f1 = Xg[row * 32 + ch * 2 + 1];
            float f[8] = {f0.x, f0.y, f0.z, f0.w, f1.x, f1.y, f1.z, f1.w};
            uint4 hi, lo;
            cvt8(f, hi, lo);
            int off = row * 256 + ((ch ^ (row & 7)) << 4);
            *(uint4*)(smem + SOFF_AHI + off) = hi;
            *(uint4*)(smem + SOFF_ALO + off) = lo;
        }
    }

    const int wr0 = (w & 1) * 32;
    const int wc0 = (w >> 1) * 32;
    const int quad = lane >> 3;
    const int l7 = lane & 7;
    const int arow0 = wr0 + l7 + (quad & 1) * 8;
    const int arow1 = arow0 + 16;
    const int axor0 = arow0 & 7;
    const int axor1 = arow1 & 7;
    const int ac_off = quad >> 1;
    const int krow_base = l7 + (quad & 1) * 8;
    const int bxor = krow_base & 7;
    const int g = lane >> 2;
    const int t2 = lane & 3;

    const float* blist[3] = {bq, bk, bv};

#pragma unroll 1
    for (int j = 0; j < 3; ++j) {
        __syncthreads();
        {
            const uint4* src = g_wimg + j * 4096;
#pragma unroll
            for (int it = 0; it < 8; ++it) {
                int i = tid + it * 256;
                *(uint4*)(smem + SOFF_WHI + i * 16) = src[i];
                *(uint4*)(smem + SOFF_WLO + i * 16) = src[2048 + i];
            }
        }
        __syncthreads();

        float acc[2][4][4];
#pragma unroll
        for (int ii = 0; ii < 2; ++ii)
#pragma unroll
            for (int jj = 0; jj < 4; ++jj)
#pragma unroll
                for (int kk = 0; kk < 4; ++kk) acc[ii][jj][kk] = 0.f;

#pragma unroll 1
        for (int ks = 0; ks < 8; ++ks) {
            u32 ah0[4], ah1[4], al0[4], al1[4];
            {
                int offA0 = arow0 * 256 + (((ks * 2 + ac_off) ^ axor0) << 4);
                int offA1 = arow1 * 256 + (((ks * 2 + ac_off) ^ axor1) << 4);
                ldsm4(sb + SOFF_AHI + offA0, ah0[0], ah0[1], ah0[2], ah0[3]);
                ldsm4(sb + SOFF_ALO + offA0, al0[0], al0[1], al0[2], al0[3]);
                ldsm4(sb + SOFF_AHI + offA1, ah1[0], ah1[1], ah1[2], ah1[3]);
                ldsm4(sb + SOFF_ALO + offA1, al1[0], al1[1], al1[2], al1[3]);
            }
#pragma unroll
            for (int p = 0; p < 2; ++p) {
                int chB = (wc0 >> 3) + p * 2 + (quad >> 1);
                int offB = (ks * 16 + krow_base) * 256 + ((chB ^ bxor) << 4);
                u32 wb0, wb1, wb2, wb3;
                ldsm4t(sb + SOFF_WHI + offB, wb0, wb1, wb2, wb3);
                mma_bf16(acc[0][2 * p],     ah0[0], ah0[1], ah0[2], ah0[3], wb0, wb1);
                mma_bf16(acc[0][2 * p + 1], ah0[0], ah0[1], ah0[2], ah0[3], wb2, wb3);
                mma_bf16(acc[1][2 * p],     ah1[0], ah1[1], ah1[2], ah1[3], wb0, wb1);
                mma_bf16(acc[1][2 * p + 1], ah1[0], ah1[1], ah1[2], ah1[3], wb2, wb3);
                mma_bf16(acc[0][2 * p],     al0[0], al0[1], al0[2], al0[3], wb0, wb1);
                mma_bf16(acc[0][2 * p + 1], al0[0], al0[1], al0[2], al0[3], wb2, wb3);
                mma_bf16(acc[1][2 * p],     al1[0], al1[1], al1[2], al1[3], wb0, wb1);
                mma_bf16(acc[1][2 * p + 1], al1[0], al1[1], al1[2], al1[3], wb2, wb3);
                ldsm4t(sb + SOFF_WLO + offB, wb0, wb1, wb2, wb3);
                mma_bf16(acc[0][2 * p],     ah0[0], ah0[1], ah0[2], ah0[3], wb0, wb1);
                mma_bf16(acc[0][2 * p + 1], ah0[0], ah0[1], ah0[2], ah0[3], wb2, wb3);
                mma_bf16(acc[1][2 * p],     ah1[0], ah1[1], ah1[2], ah1[3], wb0, wb1);
                mma_bf16(acc[1][2 * p + 1], ah1[0], ah1[1], ah1[2], ah1[3], wb2, wb3);
            }
        }

        float* outp = (j == 0) ? g_q : (j == 1) ? g_k : g_v;
        const float* bias = blist[j];
        const bool act = (j < 2);
#pragma unroll
        for (int mt = 0; mt < 2; ++mt) {
#pragma unroll
            for (int nt = 0; nt < 4; ++nt) {
                int col = wc0 + nt * 8 + t2 * 2;
                float2 bb = *(const float2*)(bias + col);
                long long r0g = m0 + wr0 + mt * 16 + g;
                float v0 = acc[mt][nt][0] + bb.x;
                float v1 = acc[mt][nt][1] + bb.y;
                float v2 = acc[mt][nt][2] + bb.x;
                float v3 = acc[mt][nt][3] + bb.y;
                if (act) { v0 = elu1(v0); v1 = elu1(v1); v2 = elu1(v2); v3 = elu1(v3); }
                *(float2*)(outp + r0g * EE + col)       = make_float2(v0, v1);
                *(float2*)(outp + (r0g + 8) * EE + col) = make_float2(v2, v3);
            }
        }
    }
}

// ---------------------------------------------------------------------------
// Kernel 2: partial KtV/ksum. grid = NKV*4.
// ---------------------------------------------------------------------------
__global__ __launch_bounds__(256)
void ktv_kernel()
{
    __shared__ float sk[64][32];
    __shared__ float sv[64][32];

    const int bx = blockIdx.x;
    const int part = bx & 3;
    const int blk = bx >> 2;              // br*H + h
    const int h = blk & 3;
    const int br = blk >> 2;
    const long long base = (long long)br * CC * EE + h * DH;

    const int tid = threadIdx.x;
    const int d = tid & 31;
    const int eg = tid >> 5;

    float a0 = 0.f, a1 = 0.f, a2 = 0.f, a3 = 0.f, ks = 0.f;

    const int cbeg = part * 512;
    for (int c0 = cbeg; c0 < cbeg + 512; c0 += 64) {
        __syncthreads();
        #pragma unroll
        for (int it = 0; it < 8; ++it) {
            int idx = tid + it * 256;
            int r = idx >> 5;
            int c = idx & 31;
            long long gi = base + (long long)(c0 + r) * EE + c;
            sk[r][c] = g_k[gi];
            sv[r][c] = g_v[gi];
        }
        __syncthreads();
        #pragma unroll 8
        for (int cc = 0; cc < 64; ++cc) {
            float kd = sk[cc][d];
            float4 ve = *(const float4*)&sv[cc][eg * 4];
            a0 = fmaf(kd, ve.x, a0);
            a1 = fmaf(kd, ve.y, a1);
            a2 = fmaf(kd, ve.z, a2);
            a3 = fmaf(kd, ve.w, a3);
            ks += kd;
        }
    }

    float* ktv = g_ktv_part + (long long)bx * DH * DH;
    float4 o = {a0, a1, a2, a3};
    *(float4*)&ktv[d * 32 + eg * 4] = o;
    if (eg == 0) g_ksum_part[bx * 32 + d] = ks;
}

// ---------------------------------------------------------------------------
// Kernel 2b: reduce the 4 KtV partials, convert to bf16 hi/lo image chunks.
// grid = NKV (one block per (br,h)), 128 threads.
// g_ktvimg layout per br: [hi: (h,d,cc) 512 uint4][lo: 512 uint4]
// ---------------------------------------------------------------------------
__global__ __launch_bounds__(128)
void ktv_reduce_kernel()
{
    const int blk = blockIdx.x;           // br*H + h
    const int h = blk & 3;
    const int br = blk >> 2;
    const int t = threadIdx.x;
    const int d = t >> 2;
    const int cc = t & 3;

    const float* base = g_ktv_part + (long long)blk * 4 * 1024;
    const float4* p0 = (const float4*)(base + d * 32 + cc * 8);
    float4 a0 = p0[0], b0 = p0[1];
    const float4* p1 = (const float4*)(base + 1024 + d * 32 + cc * 8);
    float4 a1 = p1[0], b1 = p1[1];
    const float4* p2 = (const float4*)(base + 2048 + d * 32 + cc * 8);
    float4 a2 = p2[0], b2 = p2[1];
    const float4* p3 = (const float4*)(base + 3072 + d * 32 + cc * 8);
    float4 a3 = p3[0], b3 = p3[1];

    float f[8];
    f[0] = (a0.x + a1.x) + (a2.x + a3.x);
    f[1] = (a0.y + a1.y) + (a2.y + a3.y);
    f[2] = (a0.z + a1.z) + (a2.z + a3.z);
    f[3] = (a0.w + a1.w) + (a2.w + a3.w);
    f[4] = (b0.x + b1.x) + (b2.x + b3.x);
    f[5] = (b0.y + b1.y) + (b2.y + b3.y);
    f[6] = (b0.z + b1.z) + (b2.z + b3.z);
    f[7] = (b0.w + b1.w) + (b2.w + b3.w);

    uint4 hi, lo;
    cvt8(f, hi, lo);
    int idx = h * 128 + d * 4 + cc;
    g_ktvimg[(long long)br * 1024 + idx] = hi;
    g_ktvimg[(long long)br * 1024 + 512 + idx] = lo;

    if (t < 32) {
        int b0i = blk * 4 * 32 + t;
        g_ksum_final[blk * 32 + t] =
            (g_ksum_part[b0i] + g_ksum_part[b0i + 32]) +
            (g_ksum_part[b0i + 64] + g_ksum_part[b0i + 96]);
    }
}

// ---------------------------------------------------------------------------
// Kernel 3: fused t + output projection, both on tensor cores.
// Pass 1: per-head mma t = q @ KtV (K=32), Z-scale, overwrite A image in place.
// Pass 2: out = t @ Wo + bo (K=128).
// ---------------------------------------------------------------------------
__global__ __launch_bounds__(256, 2)
void tout_kernel(const float* __restrict__ bo, float* __restrict__ out)
{
    extern __shared__ char smem[];
    const u32 sb = (u32)__cvta_generic_to_shared(smem);
    float* sKsumP = (float*)(smem + SOFF_KSUMP);     // [16][9] padded
    float* sZp    = (float*)(smem + SOFF_ZP);        // [64][16]
    float* sZ     = (float*)(smem + SOFF_Z);         // [64][4]

    const int tid = threadIdx.x;
    const int lane = tid & 31;
    const int w = tid >> 5;
    const long long tile = blockIdx.x;
    const long long m0 = tile * 64;
    const int br = (int)(tile >> 5);                 // (b*R + r)

    // ---- Phase 1: copy KtV images into W region; ksum (padded) ----
    {
        const uint4* src = g_ktvimg + (long long)br * 1024;
#pragma unroll
        for (int it = 0; it < 2; ++it) {
            int i = tid + it * 256;                  // 512 chunks each hi/lo
            int h = i >> 7;
            int d = (i >> 2) & 31;
            int cc = i & 3;
            int off = (h * 32 + d) * 256 + (((h * 4 + cc) ^ (d & 7)) << 4);
            *(uint4*)(smem + SOFF_WHI + off) = src[i];
            *(uint4*)(smem + SOFF_WLO + off) = src[512 + i];
        }
        if (tid < 128) {
            int ch = tid >> 3;
            int i = tid & 7;
            sKsumP[ch * 9 + i] = g_ksum_final[br * 128 + tid];
        }
    }
    __syncthreads();

    // ---- Phase 2: load q, convert to A image, partial Z dots ----
    {
        const float4* Qg = (const float4*)(g_q + m0 * EE);
#pragma unroll
        for (int it = 0; it < 4; ++it) {
            int idx = tid + it * 256;                // 1024 chunks (row, ch)
            int row = idx >> 4;
            int ch = idx & 15;
            float4 f0 = Qg[row * 32 + ch * 2];
            float4 f1 = Qg[row * 32 + ch * 2 + 1];
            float f[8] = {f0.x, f0.y, f0.z, f0.w, f1.x, f1.y, f1.z, f1.w};
            uint4 hi, lo;
            cvt8(f, hi, lo);
            int off = row * 256 + ((ch ^ (row & 7)) << 4);
            *(uint4*)(smem + SOFF_AHI + off) = hi;
            *(uint4*)(smem + SOFF_ALO + off) = lo;
            float s = 0.f;
            const float* kp = sKsumP + ch * 9;
#pragma unroll
            for (int i = 0; i < 8; ++i) s = fmaf(f[i], kp[i], s);
            sZp[row * 16 + ch] = s;
        }
    }
    __syncthreads();

    // ---- Phase 3: Z = 1/(sum + eps) per (row, head) ----
    {
        int row = tid >> 2;
        int h = tid & 3;
        const float* zp = sZp + row * 16 + h * 4;
        sZ[row * 4 + h] = 1.0f / (((zp[0] + zp[1]) + (zp[2] + zp[3])) + 1e-6f);
    }
    __syncthreads();

    const int wr0 = (w & 1) * 32;
    const int wc0 = (w >> 1) * 32;
    const int hh = w >> 1;                 // head this warp owns
    const int quad = lane >> 3;
    const int l7 = lane & 7;
    const int arow0 = wr0 + l7 + (quad & 1) * 8;
    const int arow1 = arow0 + 16;
    const int axor0 = arow0 & 7;
    const int axor1 = arow1 & 7;
    const int ac_off = quad >> 1;
    const int krow_base = l7 + (quad & 1) * 8;
    const int bxor = krow_base & 7;
    const int g = lane >> 2;
    const int t2 = lane & 3;

    // ---- Pass 1 mma: t = q @ KtV (per-head, K=32) ----
    {
        float acc[2][4][4];
#pragma unroll
        for (int ii = 0; ii < 2; ++ii)
#pragma unroll
            for (int jj = 0; jj < 4; ++jj)
#pragma unroll
                for (int kk = 0; kk < 4; ++kk) acc[ii][jj][kk] = 0.f;

#pragma unroll
        for (int ks = 0; ks < 2; ++ks) {
            u32 ah0[4], ah1[4], al0[4], al1[4];
            {
                int chA = hh * 4 + ks * 2 + ac_off;
                int offA0 = arow0 * 256 + ((chA ^ axor0) << 4);
                int offA1 = arow1 * 256 + ((chA ^ axor1) << 4);
                ldsm4(sb + SOFF_AHI + offA0, ah0[0], ah0[1], ah0[2], ah0[3]);
                ldsm4(sb + SOFF_ALO + offA0, al0[0], al0[1], al0[2], al0[3]);
                ldsm4(sb + SOFF_AHI + offA1, ah1[0], ah1[1], ah1[2], ah1[3]);
                ldsm4(sb + SOFF_ALO + offA1, al1[0], al1[1], al1[2], al1[3]);
            }
#pragma unroll
            for (int p = 0; p < 2; ++p) {
                int chB = hh * 4 + p * 2 + (quad >> 1);
                int brow = hh * 32 + ks * 16 + krow_base;
                int offB = brow * 256 + ((chB ^ bxor) << 4);
                u32 wb0, wb1, wb2, wb3;
                ldsm4t(sb + SOFF_WHI + offB, wb0, wb1, wb2, wb3);
                mma_bf16(acc[0][2 * p],     ah0[0], ah0[1], ah0[2], ah0[3], wb0, wb1);
                mma_bf16(acc[0][2 * p + 1], ah0[0], ah0[1], ah0[2], ah0[3], wb2, wb3);
                mma_bf16(acc[1][2 * p],     ah1[0], ah1[1], ah1[2], ah1[3], wb0, wb1);
                mma_bf16(acc[1][2 * p + 1], ah1[0], ah1[1], ah1[2], ah1[3], wb2, wb3);
                mma_bf16(acc[0][2 * p],     al0[0], al0[1], al0[2], al0[3], wb0, wb1);
                mma_bf16(acc[0][2 * p + 1], al0[0], al0[1], al0[2], al0[3], wb2, wb3);
                mma_bf16(acc[1][2 * p],     al1[0], al1[1], al1[2], al1[3], wb0, wb1);
                mma_bf16(acc[1][2 * p + 1], al1[0], al1[1], al1[2], al1[3], wb2, wb3);
                ldsm4t(sb + SOFF_WLO + offB, wb0, wb1, wb2, wb3);
                mma_bf16(acc[0][2 * p],     ah0[0], ah0[1], ah0[2], ah0[3], wb0, wb1);
                mma_bf16(acc[0][2 * p + 1], ah0[0], ah0[1], ah0[2], ah0[3], wb2, wb3);
                mma_bf16(acc[1][2 * p],     ah1[0], ah1[1], ah1[2], ah1[3], wb0, wb1);
                mma_bf16(acc[1][2 * p + 1], ah1[0], ah1[1], ah1[2], ah1[3], wb2, wb3);
            }
        }

        // Z-scale + write t back into the A image (warp-local region; no sync)
#pragma unroll
        for (int mt = 0; mt < 2; ++mt) {
            int r0 = wr0 + mt * 16 + g;
            int r1 = r0 + 8;
            float z0 = sZ[r0 * 4 + hh];
            float z1 = sZ[r1 * 4 + hh];
#pragma unroll
            for (int nt = 0; nt < 4; ++nt) {
                int col = wc0 + nt * 8 + t2 * 2;
                int ch = col >> 3;
                int ib = (col & 7) * 2;
                u32 hi0, lo0, hi1, lo1;
                cvt2(acc[mt][nt][0] * z0, acc[mt][nt][1] * z0, hi0, lo0);
                cvt2(acc[mt][nt][2] * z1, acc[mt][nt][3] * z1, hi1, lo1);
                int off0 = r0 * 256 + ((ch ^ (r0 & 7)) << 4) + ib;
                int off1 = r1 * 256 + ((ch ^ (r1 & 7)) << 4) + ib;
                *(u32*)(smem + SOFF_AHI + off0) = hi0;
                *(u32*)(smem + SOFF_ALO + off0) = lo0;
                *(u32*)(smem + SOFF_AHI + off1) = hi1;
                *(u32*)(smem + SOFF_ALO + off1) = lo1;
            }
        }
    }
    __syncthreads();   // all t writes + all KtV reads done

    // ---- Phase 4: copy Wo images over KtV region ----
    {
        const uint4* wsrc = g_wimg + 3 * 4096;
#pragma unroll
        for (int it = 0; it < 8; ++it) {
            int i = tid + it * 256;
            *(uint4*)(smem + SOFF_WHI + i * 16) = wsrc[i];
            *(uint4*)(smem + SOFF_WLO + i * 16) = wsrc[2048 + i];
        }
    }
    __syncthreads();

    // ---- Pass 2 mma: out = t @ Wo + bo (K=128) ----
    float acc[2][4][4];
#pragma unroll
    for (int ii = 0; ii < 2; ++ii)
#pragma unroll
        for (int jj = 0; jj < 4; ++jj)
#pragma unroll
            for (int kk = 0; kk < 4; ++kk) acc[ii][jj][kk] = 0.f;

#pragma unroll 1
    for (int ks = 0; ks < 8; ++ks) {
        u32 ah0[4], ah1[4], al0[4], al1[4];
        {
            int offA0 = arow0 * 256 + (((ks * 2 + ac_off) ^ axor0) << 4);
            int offA1 = arow1 * 256 + (((ks * 2 + ac_off) ^ axor1) << 4);
            ldsm4(sb + SOFF_AHI + offA0, ah0[0], ah0[1], ah0[2], ah0[3]);
            ldsm4(sb + SOFF_ALO + offA0, al0[0], al0[1], al0[2], al0[3]);
            ldsm4(sb + SOFF_AHI + offA1, ah1[0], ah1[1], ah1[2], ah1[3]);
            ldsm4(sb + SOFF_ALO + offA1, al1[0], al1[1], al1[2], al1[3]);
        }
#pragma unroll
        for (int p = 0; p < 2; ++p) {
            int chB = (wc0 >> 3) + p * 2 + (quad >> 1);
            int offB = (ks * 16 + krow_base) * 256 + ((chB ^ bxor) << 4);
            u32 wb0, wb1, wb2, wb3;
            ldsm4t(sb + SOFF_WHI + offB, wb0, wb1, wb2, wb3);
            mma_bf16(acc[0][2 * p],     ah0[0], ah0[1], ah0[2], ah0[3], wb0, wb1);
            mma_bf16(acc[0][2 * p + 1], ah0[0], ah0[1], ah0[2], ah0[3], wb2, wb3);
            mma_bf16(acc[1][2 * p],     ah1[0], ah1[1], ah1[2], ah1[3], wb0, wb1);
            mma_bf16(acc[1][2 * p + 1], ah1[0], ah1[1], ah1[2], ah1[3], wb2, wb3);
            mma_bf16(acc[0][2 * p],     al0[0], al0[1], al0[2], al0[3], wb0, wb1);
            mma_bf16(acc[0][2 * p + 1], al0[0], al0[1], al0[2], al0[3], wb2, wb3);
            mma_bf16(acc[1][2 * p],     al1[0], al1[1], al1[2], al1[3], wb0, wb1);
            mma_bf16(acc[1][2 * p + 1], al1[0], al1[1], al1[2], al1[3], wb2, wb3);
            ldsm4t(sb + SOFF_WLO + offB, wb0, wb1, wb2, wb3);
            mma_bf16(acc[0][2 * p],     ah0[0], ah0[1], ah0[2], ah0[3], wb0, wb1);
            mma_bf16(acc[0][2 * p + 1], ah0[0], ah0[1], ah0[2], ah0[3], wb2, wb3);
            mma_bf16(acc[1][2 * p],     ah1[0], ah1[1], ah1[2], ah1[3], wb0, wb1);
            mma_bf16(acc[1][2 * p + 1], ah1[0], ah1[1], ah1[2], ah1[3], wb2, wb3);
        }
    }

#pragma unroll
    for (int mt = 0; mt < 2; ++mt) {
#pragma unroll
        for (int nt = 0; nt < 4; ++nt) {
            int col = wc0 + nt * 8 + t2 * 2;
            float2 bb = *(const float2*)(bo + col);
            long long r0g = m0 + wr0 + mt * 16 + g;
            float v0 = acc[mt][nt][0] + bb.x;
            float v1 = acc[mt][nt][1] + bb.y;
            float v2 = acc[mt][nt][2] + bb.x;
            float v3 = acc[mt][nt][3] + bb.y;
            *(float2*)(out + r0g * EE + col)       = make_float2(v0, v1);
            *(float2*)(out + (r0g + 8) * EE + col) = make_float2(v2, v3);
        }
    }
}

// ---------------------------------------------------------------------------
extern "C" void kernel_launch(void* const* d_in, const int* in_sizes, int n_in,
                              void* d_out, int out_size)
{
    const float* X  = (const float*)d_in[0];
    const float* Wq = (const float*)d_in[1];
    const float* bq = (const float*)d_in[2];
    const float* Wk = (const float*)d_in[3];
    const float* bk = (const float*)d_in[4];
    const float* Wv = (const float*)d_in[5];
    const float* bv = (const float*)d_in[6];
    const float* Wo = (const float*)d_in[7];
    const float* bo = (const float*)d_in[8];
    float* out = (float*)d_out;

    cudaFuncSetAttribute(qkv_mma_kernel, cudaFuncAttributeMaxDynamicSharedMemorySize, SMEM_GEMM);
    cudaFuncSetAttribute(tout_kernel, cudaFuncAttributeMaxDynamicSharedMemorySize, SMEM_TOUT);

    prep_w_kernel<<<4, 256>>>(Wq, Wk, Wv, Wo);
    qkv_mma_kernel<<<NTILES, 256, SMEM_GEMM>>>(X, bq, bk, bv);
    ktv_kernel<<<NKV * 4, 256>>>();
    ktv_reduce_kernel<<<NKV, 128>>>();
    tout_kernel<<<NTILES, 256, SMEM_TOUT>>>(bo, out);
}

// round 7
// speedup vs baseline: 1.3829x; 1.1422x over previous
#include <cuda_runtime.h>
#include <cuda_bf16.h>
#include <math.h>

typedef unsigned int u32;

// Problem constants
constexpr int BB = 2, RR = 64, CC = 2048, EE = 128, HH = 4, DH = 32;
constexpr long long MROWS = (long long)BB * RR * CC;        // 262144
constexpr long long QKV_ELEMS = MROWS * EE;                  // 33,554,432
constexpr int NTILES = (int)(MROWS / 64);                    // 4096
constexpr int NKV = BB * RR * HH;                            // 512
constexpr int NBR = BB * RR;                                 // 128

// Scratch (device globals — no runtime allocation)
__device__ float g_q[QKV_ELEMS];                             // 134 MB
__device__ float g_part[(long long)NTILES * HH * DH * DH];   // 67 MB KtV partials
__device__ float g_ksum_part[NTILES * EE];                   // 2 MB
__device__ float g_ksum_final[NKV * DH];                     // 64 KB
// Pre-swizzled bf16 weight images: [matrix 0..3][hi 2048 | lo 2048] uint4 chunks
__device__ uint4 g_wimg[4 * 4096];
// Pre-swizzled bf16 KtV images: per br: [hi 512 | lo 512] uint4 (h,d,cc)
__device__ uint4 g_ktvimg[NBR * 1024];

// ---------------------------------------------------------------------------
// helpers
// ---------------------------------------------------------------------------
__device__ __forceinline__ void ldsm4(u32 a, u32& r0, u32& r1, u32& r2, u32& r3) {
    asm volatile("ldmatrix.sync.aligned.m8n8.x4.shared.b16 {%0,%1,%2,%3},[%4];"
                 : "=r"(r0), "=r"(r1), "=r"(r2), "=r"(r3) : "r"(a));
}
__device__ __forceinline__ void ldsm4t(u32 a, u32& r0, u32& r1, u32& r2, u32& r3) {
    asm volatile("ldmatrix.sync.aligned.m8n8.x4.trans.shared.b16 {%0,%1,%2,%3},[%4];"
                 : "=r"(r0), "=r"(r1), "=r"(r2), "=r"(r3) : "r"(a));
}
__device__ __forceinline__ void mma_bf16(float c[4], const u32 a[4], u32 b0, u32 b1) {
    asm volatile(
        "mma.sync.aligned.m16n8k16.row.col.f32.bf16.bf16.f32 "
        "{%0,%1,%2,%3},{%4,%5,%6,%7},{%8,%9},{%0,%1,%2,%3};"
        : "+f"(c[0]), "+f"(c[1]), "+f"(c[2]), "+f"(c[3])
        : "r"(a[0]), "r"(a[1]), "r"(a[2]), "r"(a[3]), "r"(b0), "r"(b1));
}

__device__ __forceinline__ void cvt2(float a, float b, u32& hi, u32& lo) {
    __nv_bfloat16 ah16 = __float2bfloat16_rn(a);
    __nv_bfloat16 bh16 = __float2bfloat16_rn(b);
    float ar = a - __bfloat162float(ah16);
    float br = b - __bfloat162float(bh16);
    __nv_bfloat162 hp = __halves2bfloat162(ah16, bh16);
    __nv_bfloat162 lp = __floats2bfloat162_rn(ar, br);
    hi = *(u32*)&hp;
    lo = *(u32*)&lp;
}

// Convert 8 consecutive floats to hi/lo bf16 packed as uint4 each.
__device__ __forceinline__ void cvt8(const float* f, uint4& hi, uint4& lo) {
    u32 h[4];
    u32 l[4];
#pragma unroll
    for (int i = 0; i < 4; ++i) cvt2(f[2 * i], f[2 * i + 1], h[i], l[i]);
    hi = make_uint4(h[0], h[1], h[2], h[3]);
    lo = make_uint4(l[0], l[1], l[2], l[3]);
}

__device__ __forceinline__ float elu1(float x) {
    return (x > 0.f) ? (x + 1.f) : expf(x);
}

// ---- smem layout (bytes), fused kernel ----
// Xhi [0,16K) Xlo [16K,32K)
// W slot [32K,64K): Whi or Wlo (two-pass); later v image (vhi 16K + vlo 16K)
// k image [64K,96K): khi 16K + klo 16K; later KtV cross-warp scratch (16K at 64K)
// ksum scratch [96K, 97K)
constexpr int SOFF_XHI = 0;
constexpr int SOFF_XLO = 16384;
constexpr int SOFF_W   = 32768;
constexpr int SOFF_VHI = 32768;
constexpr int SOFF_VLO = 49152;
constexpr int SOFF_KHI = 65536;
constexpr int SOFF_KLO = 81920;
constexpr int SOFF_SCR = 65536;
constexpr int SOFF_KS2 = 98304;
constexpr int SMEM_FUSED = 98304 + 1024;   // 99328

// ---- tout smem layout (same as round 6) ----
constexpr int SOFF_AHI = 0;
constexpr int SOFF_ALO = 16384;
constexpr int SOFF_WHI2 = 32768;
constexpr int SOFF_WLO2 = 65536;
constexpr int SOFF_KSUMP = 98304;
constexpr int SOFF_ZP    = 98304 + 576;
constexpr int SOFF_Z     = 98304 + 576 + 4096;
constexpr int SMEM_TOUT  = SOFF_Z + 1024;

// ---------------------------------------------------------------------------
// Kernel 0: precompute bf16 hi/lo swizzled images of the 4 weight matrices.
// ---------------------------------------------------------------------------
__global__ __launch_bounds__(256)
void prep_w_kernel(const float* __restrict__ Wq, const float* __restrict__ Wk,
                   const float* __restrict__ Wv, const float* __restrict__ Wo)
{
    const float* Ws[4] = {Wq, Wk, Wv, Wo};
    const float4* W = (const float4*)Ws[blockIdx.x];
    uint4* dst = g_wimg + blockIdx.x * 4096;
    const int tid = threadIdx.x;
#pragma unroll
    for (int it = 0; it < 8; ++it) {
        int idx = tid + it * 256;            // 2048 chunks
        int row = idx >> 4;
        int ch = idx & 15;
        float4 f0 = W[row * 32 + ch * 2];
        float4 f1 = W[row * 32 + ch * 2 + 1];
        float f[8] = {f0.x, f0.y, f0.z, f0.w, f1.x, f1.y, f1.z, f1.w};
        uint4 hi, lo;
        cvt8(f, hi, lo);
        int c = row * 16 + (ch ^ (row & 7));
        dst[c] = hi;
        dst[2048 + c] = lo;
    }
}

// ---------------------------------------------------------------------------
// Projection mma: two-pass over W (hi then lo), accumulating 3-term split.
// acc must be zeroed by caller. Syncs internally (block-wide).
// ---------------------------------------------------------------------------
__device__ __forceinline__ void proj_mma(char* smem, u32 sb, const uint4* wsrc,
                                         float acc[2][4][4])
{
    const int tid = threadIdx.x;
    const int lane = tid & 31;
    const int w = tid >> 5;
    const int wr0 = (w & 1) * 32;
    const int wc0 = (w >> 1) * 32;
    const int quad = lane >> 3;
    const int l7 = lane & 7;
    const int arow0 = wr0 + l7 + (quad & 1) * 8;
    const int arow1 = arow0 + 16;
    const int axor0 = arow0 & 7;
    const int axor1 = arow1 & 7;
    const int ac_off = quad >> 1;
    const int krow_base = l7 + (quad & 1) * 8;
    const int bxor = krow_base & 7;

    // ---- pass 1: W hi (terms Xhi*Whi + Xlo*Whi) ----
    __syncthreads();
#pragma unroll
    for (int it = 0; it < 8; ++it) {
        int i = tid + it * 256;
        *(uint4*)(smem + SOFF_W + i * 16) = wsrc[i];
    }
    __syncthreads();
#pragma unroll 1
    for (int ks = 0; ks < 8; ++ks) {
        u32 ah0[4], ah1[4], al0[4], al1[4];
        int offA0 = arow0 * 256 + (((ks * 2 + ac_off) ^ axor0) << 4);
        int offA1 = arow1 * 256 + (((ks * 2 + ac_off) ^ axor1) << 4);
        ldsm4(sb + SOFF_XHI + offA0, ah0[0], ah0[1], ah0[2], ah0[3]);
        ldsm4(sb + SOFF_XLO + offA0, al0[0], al0[1], al0[2], al0[3]);
        ldsm4(sb + SOFF_XHI + offA1, ah1[0], ah1[1], ah1[2], ah1[3]);
        ldsm4(sb + SOFF_XLO + offA1, al1[0], al1[1], al1[2], al1[3]);
#pragma unroll
        for (int p = 0; p < 2; ++p) {
            int chB = (wc0 >> 3) + p * 2 + (quad >> 1);
            int offB = (ks * 16 + krow_base) * 256 + ((chB ^ bxor) << 4);
            u32 wb0, wb1, wb2, wb3;
            ldsm4t(sb + SOFF_W + offB, wb0, wb1, wb2, wb3);
            mma_bf16(acc[0][2 * p],     ah0, wb0, wb1);
            mma_bf16(acc[0][2 * p + 1], ah0, wb2, wb3);
            mma_bf16(acc[1][2 * p],     ah1, wb0, wb1);
            mma_bf16(acc[1][2 * p + 1], ah1, wb2, wb3);
            mma_bf16(acc[0][2 * p],     al0, wb0, wb1);
            mma_bf16(acc[0][2 * p + 1], al0, wb2, wb3);
            mma_bf16(acc[1][2 * p],     al1, wb0, wb1);
            mma_bf16(acc[1][2 * p + 1], al1, wb2, wb3);
        }
    }
    // ---- pass 2: W lo (term Xhi*Wlo) ----
    __syncthreads();
#pragma unroll
    for (int it = 0; it < 8; ++it) {
        int i = tid + it * 256;
        *(uint4*)(smem + SOFF_W + i * 16) = wsrc[2048 + i];
    }
    __syncthreads();
#pragma unroll 1
    for (int ks = 0; ks < 8; ++ks) {
        u32 ah0[4], ah1[4];
        int offA0 = arow0 * 256 + (((ks * 2 + ac_off) ^ axor0) << 4);
        int offA1 = arow1 * 256 + (((ks * 2 + ac_off) ^ axor1) << 4);
        ldsm4(sb + SOFF_XHI + offA0, ah0[0], ah0[1], ah0[2], ah0[3]);
        ldsm4(sb + SOFF_XHI + offA1, ah1[0], ah1[1], ah1[2], ah1[3]);
#pragma unroll
        for (int p = 0; p < 2; ++p) {
            int chB = (wc0 >> 3) + p * 2 + (quad >> 1);
            int offB = (ks * 16 + krow_base) * 256 + ((chB ^ bxor) << 4);
            u32 wb0, wb1, wb2, wb3;
            ldsm4t(sb + SOFF_W + offB, wb0, wb1, wb2, wb3);
            mma_bf16(acc[0][2 * p],     ah0, wb0, wb1);
            mma_bf16(acc[0][2 * p + 1], ah0, wb2, wb3);
            mma_bf16(acc[1][2 * p],     ah1, wb0, wb1);
            mma_bf16(acc[1][2 * p + 1], ah1, wb2, wb3);
        }
    }
}

// ---------------------------------------------------------------------------
// Kernel 1: fused QKV projection + per-tile KtV/ksum partials.
// Per block: 64 rows. Phases: X load; k proj (->smem image, ksum); v proj
// (->smem image); KtV mma (tensor); partial store; q proj (->g_q f32).
// ---------------------------------------------------------------------------
__global__ __launch_bounds__(256, 2)
void fused_qkv_ktv_kernel(const float* __restrict__ X,
                          const float* __restrict__ bq,
                          const float* __restrict__ bk,
                          const float* __restrict__ bv)
{
    extern __shared__ char smem[];
    const u32 sb = (u32)__cvta_generic_to_shared(smem);
    float* ks2 = (float*)(smem + SOFF_KS2);          // [2][128]
    float* scr = (float*)(smem + SOFF_SCR);          // [4][1024] (post-KtV)

    const int tid = threadIdx.x;
    const int lane = tid & 31;
    const int w = tid >> 5;
    const long long tile = blockIdx.x;
    const long long m0 = tile * 64;

    // ---- Load + convert X tile (64x128 f32 -> bf16 hi/lo, swizzled) ----
    {
        const float4* Xg = (const float4*)(X + m0 * EE);
#pragma unroll
        for (int it = 0; it < 4; ++it) {
            int idx = tid + it * 256;            // 1024 chunks (row, ch)
            int row = idx >> 4;
            int ch = idx & 15;
            float4 f0 = Xg[row * 32 + ch * 2];
            float4 f1 = Xg[row * 32 + ch * 2 + 1];
            float f[8] = {f0.x, f0.y, f0.z, f0.w, f1.x, f1.y, f1.z, f1.w};
            uint4 hi, lo;
            cvt8(f, hi, lo);
            int off = row * 256 + ((ch ^ (row & 7)) << 4);
            *(uint4*)(smem + SOFF_XHI + off) = hi;
            *(uint4*)(smem + SOFF_XLO + off) = lo;
        }
    }

    const int wr0 = (w & 1) * 32;
    const int wc0 = (w >> 1) * 32;
    const int quad = lane >> 3;
    const int l7 = lane & 7;
    const int g = lane >> 2;
    const int t2 = lane & 3;

    float acc[2][4][4];

    // ================= Phase k =================
#pragma unroll
    for (int ii = 0; ii < 2; ++ii)
#pragma unroll
        for (int jj = 0; jj < 4; ++jj)
#pragma unroll
            for (int kk = 0; kk < 4; ++kk) acc[ii][jj][kk] = 0.f;
    proj_mma(smem, sb, g_wimg + 1 * 4096, acc);   // Wk

    // epilogue: bias + elu -> k image (smem) + ksum partial (shfl)
    {
        float ssum[4][2];
#pragma unroll
        for (int nt = 0; nt < 4; ++nt) { ssum[nt][0] = 0.f; ssum[nt][1] = 0.f; }
#pragma unroll
        for (int mt = 0; mt < 2; ++mt) {
            int r0 = wr0 + mt * 16 + g;
            int r1 = r0 + 8;
#pragma unroll
            for (int nt = 0; nt < 4; ++nt) {
                int col = wc0 + nt * 8 + t2 * 2;
                float2 bb = *(const float2*)(bk + col);
                float v0 = elu1(acc[mt][nt][0] + bb.x);
                float v1 = elu1(acc[mt][nt][1] + bb.y);
                float v2 = elu1(acc[mt][nt][2] + bb.x);
                float v3 = elu1(acc[mt][nt][3] + bb.y);
                ssum[nt][0] += v0 + v2;
                ssum[nt][1] += v1 + v3;
                int ch = col >> 3;
                int ib = (col & 7) * 2;
                u32 hi0, lo0, hi1, lo1;
                cvt2(v0, v1, hi0, lo0);
                cvt2(v2, v3, hi1, lo1);
                int off0 = r0 * 256 + ((ch ^ (r0 & 7)) << 4) + ib;
                int off1 = r1 * 256 + ((ch ^ (r1 & 7)) << 4) + ib;
                *(u32*)(smem + SOFF_KHI + off0) = hi0;
                *(u32*)(smem + SOFF_KLO + off0) = lo0;
                *(u32*)(smem + SOFF_KHI + off1) = hi1;
                *(u32*)(smem + SOFF_KLO + off1) = lo1;
            }
        }
        // reduce over g (lane bits 2..4)
#pragma unroll
        for (int nt = 0; nt < 4; ++nt) {
#pragma unroll
            for (int j = 0; j < 2; ++j) {
                float s = ssum[nt][j];
                s += __shfl_xor_sync(0xffffffffu, s, 4);
                s += __shfl_xor_sync(0xffffffffu, s, 8);
                s += __shfl_xor_sync(0xffffffffu, s, 16);
                ssum[nt][j] = s;
            }
        }
        if (lane < 4) {
#pragma unroll
            for (int nt = 0; nt < 4; ++nt) {
                ks2[(w & 1) * 128 + wc0 + nt * 8 + lane * 2]     = ssum[nt][0];
                ks2[(w & 1) * 128 + wc0 + nt * 8 + lane * 2 + 1] = ssum[nt][1];
            }
        }
    }

    // ================= Phase v =================
#pragma unroll
    for (int ii = 0; ii < 2; ++ii)
#pragma unroll
        for (int jj = 0; jj < 4; ++jj)
#pragma unroll
            for (int kk = 0; kk < 4; ++kk) acc[ii][jj][kk] = 0.f;
    proj_mma(smem, sb, g_wimg + 2 * 4096, acc);   // Wv

    __syncthreads();   // Wv_lo reads done before overwriting W slot with v image
    {
#pragma unroll
        for (int mt = 0; mt < 2; ++mt) {
            int r0 = wr0 + mt * 16 + g;
            int r1 = r0 + 8;
#pragma unroll
            for (int nt = 0; nt < 4; ++nt) {
                int col = wc0 + nt * 8 + t2 * 2;
                float2 bb = *(const float2*)(bv + col);
                float v0 = acc[mt][nt][0] + bb.x;
                float v1 = acc[mt][nt][1] + bb.y;
                float v2 = acc[mt][nt][2] + bb.x;
                float v3 = acc[mt][nt][3] + bb.y;
                int ch = col >> 3;
                int ib = (col & 7) * 2;
                u32 hi0, lo0, hi1, lo1;
                cvt2(v0, v1, hi0, lo0);
                cvt2(v2, v3, hi1, lo1);
                int off0 = r0 * 256 + ((ch ^ (r0 & 7)) << 4) + ib;
                int off1 = r1 * 256 + ((ch ^ (r1 & 7)) << 4) + ib;
                *(u32*)(smem + SOFF_VHI + off0) = hi0;
                *(u32*)(smem + SOFF_VLO + off0) = lo0;
                *(u32*)(smem + SOFF_VHI + off1) = hi1;
                *(u32*)(smem + SOFF_VLO + off1) = lo1;
            }
        }
    }
    __syncthreads();   // k/v images visible to all

    // ================= Phase KtV (tensor) =================
    // warp w: head hh = w>>1, c-half = w&1. A = k^T (ldsm trans), B = v.
    {
        const int hh = w >> 1;
        const int cb = (w & 1) * 32;
#pragma unroll
        for (int ii = 0; ii < 2; ++ii)
#pragma unroll
            for (int jj = 0; jj < 4; ++jj)
#pragma unroll
                for (int kk = 0; kk < 4; ++kk) acc[ii][jj][kk] = 0.f;

#pragma unroll
        for (int ks = 0; ks < 2; ++ks) {
            u32 akh[2][4], akl[2][4];
            {
                int crowA = cb + ks * 16 + l7 + (quad >> 1) * 8;
                int ax = crowA & 7;
#pragma unroll
                for (int mt = 0; mt < 2; ++mt) {
                    int chA = hh * 4 + mt * 2 + (quad & 1);
                    int offA = crowA * 256 + ((chA ^ ax) << 4);
                    ldsm4t(sb + SOFF_KHI + offA, akh[mt][0], akh[mt][1], akh[mt][2], akh[mt][3]);
                    ldsm4t(sb + SOFF_KLO + offA, akl[mt][0], akl[mt][1], akl[mt][2], akl[mt][3]);
                }
            }
            int crowB = cb + ks * 16 + l7 + (quad & 1) * 8;
            int bx = crowB & 7;
#pragma unroll
            for (int p = 0; p < 2; ++p) {
                int chB = hh * 4 + p * 2 + (quad >> 1);
                int offB = crowB * 256 + ((chB ^ bx) << 4);
                u32 wb0, wb1, wb2, wb3;
                ldsm4t(sb + SOFF_VHI + offB, wb0, wb1, wb2, wb3);
                mma_bf16(acc[0][2 * p],     akh[0], wb0, wb1);
                mma_bf16(acc[0][2 * p + 1], akh[0], wb2, wb3);
                mma_bf16(acc[1][2 * p],     akh[1], wb0, wb1);
                mma_bf16(acc[1][2 * p + 1], akh[1], wb2, wb3);
                mma_bf16(acc[0][2 * p],     akl[0], wb0, wb1);
                mma_bf16(acc[0][2 * p + 1], akl[0], wb2, wb3);
                mma_bf16(acc[1][2 * p],     akl[1], wb0, wb1);
                mma_bf16(acc[1][2 * p + 1], akl[1], wb2, wb3);
                ldsm4t(sb + SOFF_VLO + offB, wb0, wb1, wb2, wb3);
                mma_bf16(acc[0][2 * p],     akh[0], wb0, wb1);
                mma_bf16(acc[0][2 * p + 1], akh[0], wb2, wb3);
                mma_bf16(acc[1][2 * p],     akh[1], wb0, wb1);
                mma_bf16(acc[1][2 * p + 1], akh[1], wb2, wb3);
            }
        }
        __syncthreads();   // k image reads done; scratch region free

        if (w & 1) {
#pragma unroll
            for (int mt = 0; mt < 2; ++mt) {
#pragma unroll
                for (int nt = 0; nt < 4; ++nt) {
                    int i0 = (mt * 16 + g) * 32 + nt * 8 + t2 * 2;
                    int i1 = (mt * 16 + g + 8) * 32 + nt * 8 + t2 * 2;
                    *(float2*)(scr + hh * 1024 + i0) = make_float2(acc[mt][nt][0], acc[mt][nt][1]);
                    *(float2*)(scr + hh * 1024 + i1) = make_float2(acc[mt][nt][2], acc[mt][nt][3]);
                }
            }
        }
        __syncthreads();
        if (!(w & 1)) {
            float* dst = g_part + tile * 4096 + hh * 1024;
#pragma unroll
            for (int mt = 0; mt < 2; ++mt) {
#pragma unroll
                for (int nt = 0; nt < 4; ++nt) {
                    int i0 = (mt * 16 + g) * 32 + nt * 8 + t2 * 2;
                    int i1 = (mt * 16 + g + 8) * 32 + nt * 8 + t2 * 2;
                    float2 s0 = *(const float2*)(scr + hh * 1024 + i0);
                    float2 s1 = *(const float2*)(scr + hh * 1024 + i1);
                    *(float2*)(dst + i0) = make_float2(acc[mt][nt][0] + s0.x, acc[mt][nt][1] + s0.y);
                    *(float2*)(dst + i1) = make_float2(acc[mt][nt][2] + s1.x, acc[mt][nt][3] + s1.y);
                }
            }
        }
        if (tid < 128)
            g_ksum_part[tile * 128 + tid] = ks2[tid] + ks2[128 + tid];
    }

    // ================= Phase q =================
#pragma unroll
    for (int ii = 0; ii < 2; ++ii)
#pragma unroll
        for (int jj = 0; jj < 4; ++jj)
#pragma unroll
            for (int kk = 0; kk < 4; ++kk) acc[ii][jj][kk] = 0.f;
    proj_mma(smem, sb, g_wimg + 0 * 4096, acc);   // Wq

    {
#pragma unroll
        for (int mt = 0; mt < 2; ++mt) {
#pragma unroll
            for (int nt = 0; nt < 4; ++nt) {
                int col = wc0 + nt * 8 + t2 * 2;
                float2 bb = *(const float2*)(bq + col);
                long long r0g = m0 + wr0 + mt * 16 + g;
                float v0 = elu1(acc[mt][nt][0] + bb.x);
                float v1 = elu1(acc[mt][nt][1] + bb.y);
                float v2 = elu1(acc[mt][nt][2] + bb.x);
                float v3 = elu1(acc[mt][nt][3] + bb.y);
                *(float2*)(g_q + r0g * EE + col)       = make_float2(v0, v1);
                *(float2*)(g_q + (r0g + 8) * EE + col) = make_float2(v2, v3);
            }
        }
    }
}

// ---------------------------------------------------------------------------
// Kernel 2: reduce 32 tile-partials per (br,h) -> bf16 images + final ksum.
// ---------------------------------------------------------------------------
__global__ __launch_bounds__(128)
void ktv_reduce_kernel()
{
    const int blk = blockIdx.x;           // br*H + h
    const int h = blk & 3;
    const int br = blk >> 2;
    const int t = threadIdx.x;
    const int d = t >> 2;
    const int cc = t & 3;

    float f[8];
#pragma unroll
    for (int i = 0; i < 8; ++i) f[i] = 0.f;
#pragma unroll 4
    for (int i = 0; i < 32; ++i) {
        const float4* p = (const float4*)(g_part + ((long long)(br * 32 + i)) * 4096 +
                                          h * 1024 + d * 32 + cc * 8);
        float4 a = p[0];
        float4 b = p[1];
        f[0] += a.x; f[1] += a.y; f[2] += a.z; f[3] += a.w;
        f[4] += b.x; f[5] += b.y; f[6] += b.z; f[7] += b.w;
    }
    uint4 hi, lo;
    cvt8(f, hi, lo);
    int idx = h * 128 + d * 4 + cc;
    g_ktvimg[(long long)br * 1024 + idx] = hi;
    g_ktvimg[(long long)br * 1024 + 512 + idx] = lo;

    if (t < 32) {
        float s = 0.f;
#pragma unroll 4
        for (int i = 0; i < 32; ++i)
            s += g_ksum_part[(br * 32 + i) * 128 + h * 32 + t];
        g_ksum_final[blk * 32 + t] = s;
    }
}

// ---------------------------------------------------------------------------
// Kernel 3: fused t + output projection, both on tensor cores (round-6 proven).
// ---------------------------------------------------------------------------
__global__ __launch_bounds__(256, 2)
void tout_kernel(const float* __restrict__ bo, float* __restrict__ out)
{
    extern __shared__ char smem[];
    const u32 sb = (u32)__cvta_generic_to_shared(smem);
    float* sKsumP = (float*)(smem + SOFF_KSUMP);     // [16][9] padded
    float* sZp    = (float*)(smem + SOFF_ZP);        // [64][16]
    float* sZ     = (float*)(smem + SOFF_Z);         // [64][4]

    const int tid = threadIdx.x;
    const int lane = tid & 31;
    const int w = tid >> 5;
    const long long tile = blockIdx.x;
    const long long m0 = tile * 64;
    const int br = (int)(tile >> 5);

    // ---- Phase 1: copy KtV images into W region; ksum (padded) ----
    {
        const uint4* src = g_ktvimg + (long long)br * 1024;
#pragma unroll
        for (int it = 0; it < 2; ++it) {
            int i = tid + it * 256;
            int h = i >> 7;
            int d = (i >> 2) & 31;
            int cc = i & 3;
            int off = (h * 32 + d) * 256 + (((h * 4 + cc) ^ (d & 7)) << 4);
            *(uint4*)(smem + SOFF_WHI2 + off) = src[i];
            *(uint4*)(smem + SOFF_WLO2 + off) = src[512 + i];
        }
        if (tid < 128) {
            int ch = tid >> 3;
            int i = tid & 7;
            sKsumP[ch * 9 + i] = g_ksum_final[br * 128 + tid];
        }
    }
    __syncthreads();

    // ---- Phase 2: load q, convert to A image, partial Z dots ----
    {
        const float4* Qg = (const float4*)(g_q + m0 * EE);
#pragma unroll
        for (int it = 0; it < 4; ++it) {
            int idx = tid + it * 256;
            int row = idx >> 4;
            int ch = idx & 15;
            float4 f0 = Qg[row * 32 + ch * 2];
            float4 f1 = Qg[row * 32 + ch * 2 + 1];
            float f[8] = {f0.x, f0.y, f0.z, f0.w, f1.x, f1.y, f1.z, f1.w};
            uint4 hi, lo;
            cvt8(f, hi, lo);
            int off = row * 256 + ((ch ^ (row & 7)) << 4);
            *(uint4*)(smem + SOFF_AHI + off) = hi;
            *(uint4*)(smem + SOFF_ALO + off) = lo;
            float s = 0.f;
            const float* kp = sKsumP + ch * 9;
#pragma unroll
            for (int i = 0; i < 8; ++i) s = fmaf(f[i], kp[i], s);
            sZp[row * 16 + ch] = s;
        }
    }
    __syncthreads();

    // ---- Phase 3: Z = 1/(sum + eps) per (row, head) ----
    {
        int row = tid >> 2;
        int h = tid & 3;
        const float* zp = sZp + row * 16 + h * 4;
        sZ[row * 4 + h] = 1.0f / (((zp[0] + zp[1]) + (zp[2] + zp[3])) + 1e-6f);
    }
    __syncthreads();

    const int wr0 = (w & 1) * 32;
    const int wc0 = (w >> 1) * 32;
    const int hh = w >> 1;
    const int quad = lane >> 3;
    const int l7 = lane & 7;
    const int arow0 = wr0 + l7 + (quad & 1) * 8;
    const int arow1 = arow0 + 16;
    const int axor0 = arow0 & 7;
    const int axor1 = arow1 & 7;
    const int ac_off = quad >> 1;
    const int krow_base = l7 + (quad & 1) * 8;
    const int bxor = krow_base & 7;
    const int g = lane >> 2;
    const int t2 = lane & 3;

    // ---- Pass 1 mma: t = q @ KtV (per-head, K=32) ----
    {
        float acc[2][4][4];
#pragma unroll
        for (int ii = 0; ii < 2; ++ii)
#pragma unroll
            for (int jj = 0; jj < 4; ++jj)
#pragma unroll
                for (int kk = 0; kk < 4; ++kk) acc[ii][jj][kk] = 0.f;

#pragma unroll
        for (int ks = 0; ks < 2; ++ks) {
            u32 ah0[4], ah1[4], al0[4], al1[4];
            {
                int chA = hh * 4 + ks * 2 + ac_off;
                int offA0 = arow0 * 256 + ((chA ^ axor0) << 4);
                int offA1 = arow1 * 256 + ((chA ^ axor1) << 4);
                ldsm4(sb + SOFF_AHI + offA0, ah0[0], ah0[1], ah0[2], ah0[3]);
                ldsm4(sb + SOFF_ALO + offA0, al0[0], al0[1], al0[2], al0[3]);
                ldsm4(sb + SOFF_AHI + offA1, ah1[0], ah1[1], ah1[2], ah1[3]);
                ldsm4(sb + SOFF_ALO + offA1, al1[0], al1[1], al1[2], al1[3]);
            }
#pragma unroll
            for (int p = 0; p < 2; ++p) {
                int chB = hh * 4 + p * 2 + (quad >> 1);
                int brow = hh * 32 + ks * 16 + krow_base;
                int offB = brow * 256 + ((chB ^ bxor) << 4);
                u32 wb0, wb1, wb2, wb3;
                ldsm4t(sb + SOFF_WHI2 + offB, wb0, wb1, wb2, wb3);
                mma_bf16(acc[0][2 * p],     ah0, wb0, wb1);
                mma_bf16(acc[0][2 * p + 1], ah0, wb2, wb3);
                mma_bf16(acc[1][2 * p],     ah1, wb0, wb1);
                mma_bf16(acc[1][2 * p + 1], ah1, wb2, wb3);
                mma_bf16(acc[0][2 * p],     al0, wb0, wb1);
                mma_bf16(acc[0][2 * p + 1], al0, wb2, wb3);
                mma_bf16(acc[1][2 * p],     al1, wb0, wb1);
                mma_bf16(acc[1][2 * p + 1], al1, wb2, wb3);
                ldsm4t(sb + SOFF_WLO2 + offB, wb0, wb1, wb2, wb3);
                mma_bf16(acc[0][2 * p],     ah0, wb0, wb1);
                mma_bf16(acc[0][2 * p + 1], ah0, wb2, wb3);
                mma_bf16(acc[1][2 * p],     ah1, wb0, wb1);
                mma_bf16(acc[1][2 * p + 1], ah1, wb2, wb3);
            }
        }

        // Z-scale + write t back into the A image (warp-local region; no sync)
#pragma unroll
        for (int mt = 0; mt < 2; ++mt) {
            int r0 = wr0 + mt * 16 + g;
            int r1 = r0 + 8;
            float z0 = sZ[r0 * 4 + hh];
            float z1 = sZ[r1 * 4 + hh];
#pragma unroll
            for (int nt = 0; nt < 4; ++nt) {
                int col = wc0 + nt * 8 + t2 * 2;
                int ch = col >> 3;
                int ib = (col & 7) * 2;
                u32 hi0, lo0, hi1, lo1;
                cvt2(acc[mt][nt][0] * z0, acc[mt][nt][1] * z0, hi0, lo0);
                cvt2(acc[mt][nt][2] * z1, acc[mt][nt][3] * z1, hi1, lo1);
                int off0 = r0 * 256 + ((ch ^ (r0 & 7)) << 4) + ib;
                int off1 = r1 * 256 + ((ch ^ (r1 & 7)) << 4) + ib;
                *(u32*)(smem + SOFF_AHI + off0) = hi0;
                *(u32*)(smem + SOFF_ALO + off0) = lo0;
                *(u32*)(smem + SOFF_AHI + off1) = hi1;
                *(u32*)(smem + SOFF_ALO + off1) = lo1;
            }
        }
    }
    __syncthreads();

    // ---- Phase 4: copy Wo images over KtV region ----
    {
        const uint4* wsrc = g_wimg + 3 * 4096;
#pragma unroll
        for (int it = 0; it < 8; ++it) {
            int i = tid + it * 256;
            *(uint4*)(smem + SOFF_WHI2 + i * 16) = wsrc[i];
            *(uint4*)(smem + SOFF_WLO2 + i * 16) = wsrc[2048 + i];
        }
    }
    __syncthreads();

    // ---- Pass 2 mma: out = t @ Wo + bo (K=128) ----
    float acc[2][4][4];
#pragma unroll
    for (int ii = 0; ii < 2; ++ii)
#pragma unroll
        for (int jj = 0; jj < 4; ++jj)
#pragma unroll
            for (int kk = 0; kk < 4; ++kk) acc[ii][jj][kk] = 0.f;

#pragma unroll 1
    for (int ks = 0; ks < 8; ++ks) {
        u32 ah0[4], ah1[4], al0[4], al1[4];
        {
            int offA0 = arow0 * 256 + (((ks * 2 + ac_off) ^ axor0) << 4);
            int offA1 = arow1 * 256 + (((ks * 2 + ac_off) ^ axor1) << 4);
            ldsm4(sb + SOFF_AHI + offA0, ah0[0], ah0[1], ah0[2], ah0[3]);
            ldsm4(sb + SOFF_ALO + offA0, al0[0], al0[1], al0[2], al0[3]);
            ldsm4(sb + SOFF_AHI + offA1, ah1[0], ah1[1], ah1[2], ah1[3]);
            ldsm4(sb + SOFF_ALO + offA1, al1[0], al1[1], al1[2], al1[3]);
        }
#pragma unroll
        for (int p = 0; p < 2; ++p) {
            int chB = (wc0 >> 3) + p * 2 + (quad >> 1);
            int offB = (ks * 16 + krow_base) * 256 + ((chB ^ bxor) << 4);
            u32 wb0, wb1, wb2, wb3;
            ldsm4t(sb + SOFF_WHI2 + offB, wb0, wb1, wb2, wb3);
            mma_bf16(acc[0][2 * p],     ah0, wb0, wb1);
            mma_bf16(acc[0][2 * p + 1], ah0, wb2, wb3);
            mma_bf16(acc[1][2 * p],     ah1, wb0, wb1);
            mma_bf16(acc[1][2 * p + 1], ah1, wb2, wb3);
            mma_bf16(acc[0][2 * p],     al0, wb0, wb1);
            mma_bf16(acc[0][2 * p + 1], al0, wb2, wb3);
            mma_bf16(acc[1][2 * p],     al1, wb0, wb1);
            mma_bf16(acc[1][2 * p + 1], al1, wb2, wb3);
            ldsm4t(sb + SOFF_WLO2 + offB, wb0, wb1, wb2, wb3);
            mma_bf16(acc[0][2 * p],     ah0, wb0, wb1);
            mma_bf16(acc[0][2 * p + 1], ah0, wb2, wb3);
            mma_bf16(acc[1][2 * p],     ah1, wb0, wb1);
            mma_bf16(acc[1][2 * p + 1], ah1, wb2, wb3);
        }
    }

#pragma unroll
    for (int mt = 0; mt < 2; ++mt) {
#pragma unroll
        for (int nt = 0; nt < 4; ++nt) {
            int col = wc0 + nt * 8 + t2 * 2;
            float2 bb = *(const float2*)(bo + col);
            long long r0g = m0 + wr0 + mt * 16 + g;
            float v0 = acc[mt][nt][0] + bb.x;
            float v1 = acc[mt][nt][1] + bb.y;
            float v2 = acc[mt][nt][2] + bb.x;
            float v3 = acc[mt][nt][3] + bb.y;
            *(float2*)(out + r0g * EE + col)       = make_float2(v0, v1);
            *(float2*)(out + (r0g + 8) * EE + col) = make_float2(v2, v3);
        }
    }
}

// ---------------------------------------------------------------------------
extern "C" void kernel_launch(void* const* d_in, const int* in_sizes, int n_in,
                              void* d_out, int out_size)
{
    const float* X  = (const float*)d_in[0];
    const float* Wq = (const float*)d_in[1];
    const float* bq = (const float*)d_in[2];
    const float* Wk = (const float*)d_in[3];
    const float* bk = (const float*)d_in[4];
    const float* Wv = (const float*)d_in[5];
    const float* bv = (const float*)d_in[6];
    const float* Wo = (const float*)d_in[7];
    const float* bo = (const float*)d_in[8];
    float* out = (float*)d_out;

    cudaFuncSetAttribute(fused_qkv_ktv_kernel, cudaFuncAttributeMaxDynamicSharedMemorySize, SMEM_FUSED);
    cudaFuncSetAttribute(tout_kernel, cudaFuncAttributeMaxDynamicSharedMemorySize, SMEM_TOUT);

    prep_w_kernel<<<4, 256>>>(Wq, Wk, Wv, Wo);
    fused_qkv_ktv_kernel<<<NTILES, 256, SMEM_FUSED>>>(X, bq, bk, bv);
    ktv_reduce_kernel<<<NKV, 128>>>();
    tout_kernel<<<NTILES, 256, SMEM_TOUT>>>(bo, out);
}

// round 10
// speedup vs baseline: 1.4711x; 1.0638x over previous
#include <cuda_runtime.h>
#include <cuda_bf16.h>
#include <math.h>

typedef unsigned int u32;

// Problem constants
constexpr int BB = 2, RR = 64, CC = 2048, EE = 128, HH = 4, DH = 32;
constexpr long long MROWS = (long long)BB * RR * CC;        // 262144
constexpr int NTILES = (int)(MROWS / 64);                    // 4096
constexpr int NKV = BB * RR * HH;                            // 512
constexpr int NBR = BB * RR;                                 // 128

// Scratch (device globals — no runtime allocation)
__device__ float g_part[(long long)NTILES * HH * DH * DH];   // 67 MB KtV partials
__device__ float g_ksum_part[NTILES * EE];                   // 2 MB
__device__ float g_ksum_final[NKV * DH];                     // 64 KB
// Pre-swizzled bf16 weight images: [matrix 0..3][hi 2048 | lo 2048] uint4 chunks
__device__ uint4 g_wimg[4 * 4096];
// Pre-swizzled bf16 KtV images: per br: [hi 512 | lo 512] uint4 (h,d,cc)
__device__ uint4 g_ktvimg[NBR * 1024];

// ---------------------------------------------------------------------------
// helpers
// ---------------------------------------------------------------------------
__device__ __forceinline__ void ldsm4(u32 a, u32& r0, u32& r1, u32& r2, u32& r3) {
    asm volatile("ldmatrix.sync.aligned.m8n8.x4.shared.b16 {%0,%1,%2,%3},[%4];"
                 : "=r"(r0), "=r"(r1), "=r"(r2), "=r"(r3) : "r"(a));
}
__device__ __forceinline__ void ldsm4t(u32 a, u32& r0, u32& r1, u32& r2, u32& r3) {
    asm volatile("ldmatrix.sync.aligned.m8n8.x4.trans.shared.b16 {%0,%1,%2,%3},[%4];"
                 : "=r"(r0), "=r"(r1), "=r"(r2), "=r"(r3) : "r"(a));
}
__device__ __forceinline__ void mma_bf16(float c[4], const u32 a[4], u32 b0, u32 b1) {
    asm volatile(
        "mma.sync.aligned.m16n8k16.row.col.f32.bf16.bf16.f32 "
        "{%0,%1,%2,%3},{%4,%5,%6,%7},{%8,%9},{%0,%1,%2,%3};"
        : "+f"(c[0]), "+f"(c[1]), "+f"(c[2]), "+f"(c[3])
        : "r"(a[0]), "r"(a[1]), "r"(a[2]), "r"(a[3]), "r"(b0), "r"(b1));
}

__device__ __forceinline__ void cvt2(float a, float b, u32& hi, u32& lo) {
    __nv_bfloat16 ah16 = __float2bfloat16_rn(a);
    __nv_bfloat16 bh16 = __float2bfloat16_rn(b);
    float ar = a - __bfloat162float(ah16);
    float br = b - __bfloat162float(bh16);
    __nv_bfloat162 hp = __halves2bfloat162(ah16, bh16);
    __nv_bfloat162 lp = __floats2bfloat162_rn(ar, br);
    hi = *(u32*)&hp;
    lo = *(u32*)&lp;
}

__device__ __forceinline__ void cvt8(const float* f, uint4& hi, uint4& lo) {
    u32 h[4];
    u32 l[4];
#pragma unroll
    for (int i = 0; i < 4; ++i) cvt2(f[2 * i], f[2 * i + 1], h[i], l[i]);
    hi = make_uint4(h[0], h[1], h[2], h[3]);
    lo = make_uint4(l[0], l[1], l[2], l[3]);
}

__device__ __forceinline__ float elu1(float x) {
    return (x > 0.f) ? (x + 1.f) : expf(x);
}

// ---- smem layout (bytes), fused kv/KtV kernel ----
constexpr int SOFF_XHI = 0;
constexpr int SOFF_XLO = 16384;
constexpr int SOFF_W   = 32768;
constexpr int SOFF_VHI = 32768;
constexpr int SOFF_VLO = 49152;
constexpr int SOFF_KHI = 65536;
constexpr int SOFF_KLO = 81920;
constexpr int SOFF_SCR = 65536;
constexpr int SOFF_KS2 = 98304;
constexpr int SMEM_FUSED = 98304 + 1024;   // 99328

// ---- tout smem layout: A images [0,32K), W region [32K,96K) ----
constexpr int SOFF_AHI = 0;
constexpr int SOFF_ALO = 16384;
constexpr int SOFF_WHI2 = 32768;
constexpr int SOFF_WLO2 = 65536;
constexpr int SMEM_TOUT = 98304;

// ---------------------------------------------------------------------------
// Kernel 0: precompute bf16 hi/lo swizzled images of the 4 weight matrices.
// ---------------------------------------------------------------------------
__global__ __launch_bounds__(256)
void prep_w_kernel(const float* __restrict__ Wq, const float* __restrict__ Wk,
                   const float* __restrict__ Wv, const float* __restrict__ Wo)
{
    const float* Ws[4] = {Wq, Wk, Wv, Wo};
    const float4* W = (const float4*)Ws[blockIdx.x];
    uint4* dst = g_wimg + blockIdx.x * 4096;
    const int tid = threadIdx.x;
#pragma unroll
    for (int it = 0; it < 8; ++it) {
        int idx = tid + it * 256;            // 2048 chunks
        int row = idx >> 4;
        int ch = idx & 15;
        float4 f0 = W[row * 32 + ch * 2];
        float4 f1 = W[row * 32 + ch * 2 + 1];
        float f[8] = {f0.x, f0.y, f0.z, f0.w, f1.x, f1.y, f1.z, f1.w};
        uint4 hi, lo;
        cvt8(f, hi, lo);
        int c = row * 16 + (ch ^ (row & 7));
        dst[c] = hi;
        dst[2048 + c] = lo;
    }
}

// ---------------------------------------------------------------------------
// X tile load helper: 64x128 f32 -> bf16 hi/lo swizzled images at AHI/ALO(=XHI/XLO).
// ---------------------------------------------------------------------------
__device__ __forceinline__ void load_x_images(char* smem, const float* Xg0)
{
    const int tid = threadIdx.x;
    const float4* Xg = (const float4*)Xg0;
#pragma unroll
    for (int it = 0; it < 4; ++it) {
        int idx = tid + it * 256;            // 1024 chunks (row, ch)
        int row = idx >> 4;
        int ch = idx & 15;
        float4 f0 = Xg[row * 32 + ch * 2];
        float4 f1 = Xg[row * 32 + ch * 2 + 1];
        float f[8] = {f0.x, f0.y, f0.z, f0.w, f1.x, f1.y, f1.z, f1.w};
        uint4 hi, lo;
        cvt8(f, hi, lo);
        int off = row * 256 + ((ch ^ (row & 7)) << 4);
        *(uint4*)(smem + SOFF_XHI + off) = hi;
        *(uint4*)(smem + SOFF_XLO + off) = lo;
    }
}

// ---------------------------------------------------------------------------
// Projection mma: two-pass over W (hi then lo), accumulating 3-term split.
// A = images at SOFF_XHI/XLO; W slot at SOFF_W (32KB). Syncs internally.
// ---------------------------------------------------------------------------
__device__ __forceinline__ void proj_mma(char* smem, u32 sb, const uint4* wsrc,
                                         float acc[2][4][4])
{
    const int tid = threadIdx.x;
    const int lane = tid & 31;
    const int w = tid >> 5;
    const int wr0 = (w & 1) * 32;
    const int wc0 = (w >> 1) * 32;
    const int quad = lane >> 3;
    const int l7 = lane & 7;
    const int arow0 = wr0 + l7 + (quad & 1) * 8;
    const int arow1 = arow0 + 16;
    const int axor0 = arow0 & 7;
    const int axor1 = arow1 & 7;
    const int ac_off = quad >> 1;
    const int krow_base = l7 + (quad & 1) * 8;
    const int bxor = krow_base & 7;

    // ---- pass 1: W hi (terms Xhi*Whi + Xlo*Whi) ----
    __syncthreads();
#pragma unroll
    for (int it = 0; it < 8; ++it) {
        int i = tid + it * 256;
        *(uint4*)(smem + SOFF_W + i * 16) = wsrc[i];
    }
    __syncthreads();
#pragma unroll 1
    for (int ks = 0; ks < 8; ++ks) {
        u32 ah0[4], ah1[4], al0[4], al1[4];
        int offA0 = arow0 * 256 + (((ks * 2 + ac_off) ^ axor0) << 4);
        int offA1 = arow1 * 256 + (((ks * 2 + ac_off) ^ axor1) << 4);
        ldsm4(sb + SOFF_XHI + offA0, ah0[0], ah0[1], ah0[2], ah0[3]);
        ldsm4(sb + SOFF_XLO + offA0, al0[0], al0[1], al0[2], al0[3]);
        ldsm4(sb + SOFF_XHI + offA1, ah1[0], ah1[1], ah1[2], ah1[3]);
        ldsm4(sb + SOFF_XLO + offA1, al1[0], al1[1], al1[2], al1[3]);
#pragma unroll
        for (int p = 0; p < 2; ++p) {
            int chB = (wc0 >> 3) + p * 2 + (quad >> 1);
            int offB = (ks * 16 + krow_base) * 256 + ((chB ^ bxor) << 4);
            u32 wb0, wb1, wb2, wb3;
            ldsm4t(sb + SOFF_W + offB, wb0, wb1, wb2, wb3);
            mma_bf16(acc[0][2 * p],     ah0, wb0, wb1);
            mma_bf16(acc[0][2 * p + 1], ah0, wb2, wb3);
            mma_bf16(acc[1][2 * p],     ah1, wb0, wb1);
            mma_bf16(acc[1][2 * p + 1], ah1, wb2, wb3);
            mma_bf16(acc[0][2 * p],     al0, wb0, wb1);
            mma_bf16(acc[0][2 * p + 1], al0, wb2, wb3);
            mma_bf16(acc[1][2 * p],     al1, wb0, wb1);
            mma_bf16(acc[1][2 * p + 1], al1, wb2, wb3);
        }
    }
    // ---- pass 2: W lo (term Xhi*Wlo) ----
    __syncthreads();
#pragma unroll
    for (int it = 0; it < 8; ++it) {
        int i = tid + it * 256;
        *(uint4*)(smem + SOFF_W + i * 16) = wsrc[2048 + i];
    }
    __syncthreads();
#pragma unroll 1
    for (int ks = 0; ks < 8; ++ks) {
        u32 ah0[4], ah1[4];
        int offA0 = arow0 * 256 + (((ks * 2 + ac_off) ^ axor0) << 4);
        int offA1 = arow1 * 256 + (((ks * 2 + ac_off) ^ axor1) << 4);
        ldsm4(sb + SOFF_XHI + offA0, ah0[0], ah0[1], ah0[2], ah0[3]);
        ldsm4(sb + SOFF_XHI + offA1, ah1[0], ah1[1], ah1[2], ah1[3]);
#pragma unroll
        for (int p = 0; p < 2; ++p) {
            int chB = (wc0 >> 3) + p * 2 + (quad >> 1);
            int offB = (ks * 16 + krow_base) * 256 + ((chB ^ bxor) << 4);
            u32 wb0, wb1, wb2, wb3;
            ldsm4t(sb + SOFF_W + offB, wb0, wb1, wb2, wb3);
            mma_bf16(acc[0][2 * p],     ah0, wb0, wb1);
            mma_bf16(acc[0][2 * p + 1], ah0, wb2, wb3);
            mma_bf16(acc[1][2 * p],     ah1, wb0, wb1);
            mma_bf16(acc[1][2 * p + 1], ah1, wb2, wb3);
        }
    }
}

// ---------------------------------------------------------------------------
// Kernel 1: fused K/V projection + per-tile KtV/ksum partials (q moved to tout).
// ---------------------------------------------------------------------------
__global__ __launch_bounds__(256, 2)
void fused_kv_ktv_kernel(const float* __restrict__ X,
                         const float* __restrict__ bk,
                         const float* __restrict__ bv)
{
    extern __shared__ char smem[];
    const u32 sb = (u32)__cvta_generic_to_shared(smem);
    float* ks2 = (float*)(smem + SOFF_KS2);          // [2][128]
    float* scr = (float*)(smem + SOFF_SCR);          // [4][1024] (post-KtV)

    const int tid = threadIdx.x;
    const int lane = tid & 31;
    const int w = tid >> 5;
    const long long tile = blockIdx.x;
    const long long m0 = tile * 64;

    load_x_images(smem, X + m0 * EE);

    const int wr0 = (w & 1) * 32;
    const int wc0 = (w >> 1) * 32;
    const int quad = lane >> 3;
    const int l7 = lane & 7;
    const int g = lane >> 2;
    const int t2 = lane & 3;

    float acc[2][4][4];

    // ================= Phase k =================
#pragma unroll
    for (int ii = 0; ii < 2; ++ii)
#pragma unroll
        for (int jj = 0; jj < 4; ++jj)
#pragma unroll
            for (int kk = 0; kk < 4; ++kk) acc[ii][jj][kk] = 0.f;
    proj_mma(smem, sb, g_wimg + 1 * 4096, acc);   // Wk

    // epilogue: bias + elu -> k image (smem) + ksum partial (shfl)
    {
        float ssum[4][2];
#pragma unroll
        for (int nt = 0; nt < 4; ++nt) { ssum[nt][0] = 0.f; ssum[nt][1] = 0.f; }
#pragma unroll
        for (int mt = 0; mt < 2; ++mt) {
            int r0 = wr0 + mt * 16 + g;
            int r1 = r0 + 8;
#pragma unroll
            for (int nt = 0; nt < 4; ++nt) {
                int col = wc0 + nt * 8 + t2 * 2;
                float2 bb = *(const float2*)(bk + col);
                float v0 = elu1(acc[mt][nt][0] + bb.x);
                float v1 = elu1(acc[mt][nt][1] + bb.y);
                float v2 = elu1(acc[mt][nt][2] + bb.x);
                float v3 = elu1(acc[mt][nt][3] + bb.y);
                ssum[nt][0] += v0 + v2;
                ssum[nt][1] += v1 + v3;
                int ch = col >> 3;
                int ib = (col & 7) * 2;
                u32 hi0, lo0, hi1, lo1;
                cvt2(v0, v1, hi0, lo0);
                cvt2(v2, v3, hi1, lo1);
                int off0 = r0 * 256 + ((ch ^ (r0 & 7)) << 4) + ib;
                int off1 = r1 * 256 + ((ch ^ (r1 & 7)) << 4) + ib;
                *(u32*)(smem + SOFF_KHI + off0) = hi0;
                *(u32*)(smem + SOFF_KLO + off0) = lo0;
                *(u32*)(smem + SOFF_KHI + off1) = hi1;
                *(u32*)(smem + SOFF_KLO + off1) = lo1;
            }
        }
#pragma unroll
        for (int nt = 0; nt < 4; ++nt) {
#pragma unroll
            for (int j = 0; j < 2; ++j) {
                float s = ssum[nt][j];
                s += __shfl_xor_sync(0xffffffffu, s, 4);
                s += __shfl_xor_sync(0xffffffffu, s, 8);
                s += __shfl_xor_sync(0xffffffffu, s, 16);
                ssum[nt][j] = s;
            }
        }
        if (lane < 4) {
#pragma unroll
            for (int nt = 0; nt < 4; ++nt) {
                ks2[(w & 1) * 128 + wc0 + nt * 8 + lane * 2]     = ssum[nt][0];
                ks2[(w & 1) * 128 + wc0 + nt * 8 + lane * 2 + 1] = ssum[nt][1];
            }
        }
    }

    // ================= Phase v =================
#pragma unroll
    for (int ii = 0; ii < 2; ++ii)
#pragma unroll
        for (int jj = 0; jj < 4; ++jj)
#pragma unroll
            for (int kk = 0; kk < 4; ++kk) acc[ii][jj][kk] = 0.f;
    proj_mma(smem, sb, g_wimg + 2 * 4096, acc);   // Wv

    __syncthreads();   // Wv_lo reads done before overwriting W slot with v image
    {
#pragma unroll
        for (int mt = 0; mt < 2; ++mt) {
            int r0 = wr0 + mt * 16 + g;
            int r1 = r0 + 8;
#pragma unroll
            for (int nt = 0; nt < 4; ++nt) {
                int col = wc0 + nt * 8 + t2 * 2;
                float2 bb = *(const float2*)(bv + col);
                float v0 = acc[mt][nt][0] + bb.x;
                float v1 = acc[mt][nt][1] + bb.y;
                float v2 = acc[mt][nt][2] + bb.x;
                float v3 = acc[mt][nt][3] + bb.y;
                int ch = col >> 3;
                int ib = (col & 7) * 2;
                u32 hi0, lo0, hi1, lo1;
                cvt2(v0, v1, hi0, lo0);
                cvt2(v2, v3, hi1, lo1);
                int off0 = r0 * 256 + ((ch ^ (r0 & 7)) << 4) + ib;
                int off1 = r1 * 256 + ((ch ^ (r1 & 7)) << 4) + ib;
                *(u32*)(smem + SOFF_VHI + off0) = hi0;
                *(u32*)(smem + SOFF_VLO + off0) = lo0;
                *(u32*)(smem + SOFF_VHI + off1) = hi1;
                *(u32*)(smem + SOFF_VLO + off1) = lo1;
            }
        }
    }
    __syncthreads();   // k/v images visible to all

    // ================= Phase KtV (tensor) =================
    {
        const int hh = w >> 1;
        const int cb = (w & 1) * 32;
#pragma unroll
        for (int ii = 0; ii < 2; ++ii)
#pragma unroll
            for (int jj = 0; jj < 4; ++jj)
#pragma unroll
                for (int kk = 0; kk < 4; ++kk) acc[ii][jj][kk] = 0.f;

#pragma unroll
        for (int ks = 0; ks < 2; ++ks) {
            u32 akh[2][4], akl[2][4];
            {
                int crowA = cb + ks * 16 + l7 + (quad >> 1) * 8;
                int ax = crowA & 7;
#pragma unroll
                for (int mt = 0; mt < 2; ++mt) {
                    int chA = hh * 4 + mt * 2 + (quad & 1);
                    int offA = crowA * 256 + ((chA ^ ax) << 4);
                    ldsm4t(sb + SOFF_KHI + offA, akh[mt][0], akh[mt][1], akh[mt][2], akh[mt][3]);
                    ldsm4t(sb + SOFF_KLO + offA, akl[mt][0], akl[mt][1], akl[mt][2], akl[mt][3]);
                }
            }
            int crowB = cb + ks * 16 + l7 + (quad & 1) * 8;
            int bx = crowB & 7;
#pragma unroll
            for (int p = 0; p < 2; ++p) {
                int chB = hh * 4 + p * 2 + (quad >> 1);
                int offB = crowB * 256 + ((chB ^ bx) << 4);
                u32 wb0, wb1, wb2, wb3;
                ldsm4t(sb + SOFF_VHI + offB, wb0, wb1, wb2, wb3);
                mma_bf16(acc[0][2 * p],     akh[0], wb0, wb1);
                mma_bf16(acc[0][2 * p + 1], akh[0], wb2, wb3);
                mma_bf16(acc[1][2 * p],     akh[1], wb0, wb1);
                mma_bf16(acc[1][2 * p + 1], akh[1], wb2, wb3);
                mma_bf16(acc[0][2 * p],     akl[0], wb0, wb1);
                mma_bf16(acc[0][2 * p + 1], akl[0], wb2, wb3);
                mma_bf16(acc[1][2 * p],     akl[1], wb0, wb1);
                mma_bf16(acc[1][2 * p + 1], akl[1], wb2, wb3);
                ldsm4t(sb + SOFF_VLO + offB, wb0, wb1, wb2, wb3);
                mma_bf16(acc[0][2 * p],     akh[0], wb0, wb1);
                mma_bf16(acc[0][2 * p + 1], akh[0], wb2, wb3);
                mma_bf16(acc[1][2 * p],     akh[1], wb0, wb1);
                mma_bf16(acc[1][2 * p + 1], akh[1], wb2, wb3);
            }
        }
        __syncthreads();   // k image reads done; scratch region free

        if (w & 1) {
#pragma unroll
            for (int mt = 0; mt < 2; ++mt) {
#pragma unroll
                for (int nt = 0; nt < 4; ++nt) {
                    int i0 = (mt * 16 + g) * 32 + nt * 8 + t2 * 2;
                    int i1 = (mt * 16 + g + 8) * 32 + nt * 8 + t2 * 2;
                    *(float2*)(scr + hh * 1024 + i0) = make_float2(acc[mt][nt][0], acc[mt][nt][1]);
                    *(float2*)(scr + hh * 1024 + i1) = make_float2(acc[mt][nt][2], acc[mt][nt][3]);
                }
            }
        }
        __syncthreads();
        if (!(w & 1)) {
            float* dst = g_part + tile * 4096 + hh * 1024;
#pragma unroll
            for (int mt = 0; mt < 2; ++mt) {
#pragma unroll
                for (int nt = 0; nt < 4; ++nt) {
                    int i0 = (mt * 16 + g) * 32 + nt * 8 + t2 * 2;
                    int i1 = (mt * 16 + g + 8) * 32 + nt * 8 + t2 * 2;
                    float2 s0 = *(const float2*)(scr + hh * 1024 + i0);
                    float2 s1 = *(const float2*)(scr + hh * 1024 + i1);
                    *(float2*)(dst + i0) = make_float2(acc[mt][nt][0] + s0.x, acc[mt][nt][1] + s0.y);
                    *(float2*)(dst + i1) = make_float2(acc[mt][nt][2] + s1.x, acc[mt][nt][3] + s1.y);
                }
            }
        }
        if (tid < 128)
            g_ksum_part[tile * 128 + tid] = ks2[tid] + ks2[128 + tid];
    }
}

// ---------------------------------------------------------------------------
// Kernel 2: reduce 32 tile-partials per (br,h) -> bf16 images + final ksum.
// 512 threads: 4-way partial split + smem combine.
// ---------------------------------------------------------------------------
__global__ __launch_bounds__(512)
void ktv_reduce_kernel()
{
    __shared__ float sred[512 * 9];   // padded (stride 9) to avoid bank conflicts
    __shared__ float skred[128];

    const int blk = blockIdx.x;           // br*H + h
    const int h = blk & 3;
    const int br = blk >> 2;
    const int t = threadIdx.x;
    const int chunk = t >> 2;             // 0..127 -> (d = chunk>>2, cc = chunk&3)
    const int seg = t & 3;
    const int d = chunk >> 2;
    const int cc = chunk & 3;

    float f[8];
#pragma unroll
    for (int i = 0; i < 8; ++i) f[i] = 0.f;
#pragma unroll
    for (int i = 0; i < 8; ++i) {
        int p = seg * 8 + i;
        const float4* pp = (const float4*)(g_part + ((long long)(br * 32 + p)) * 4096 +
                                           h * 1024 + d * 32 + cc * 8);
        float4 a = pp[0];
        float4 b = pp[1];
        f[0] += a.x; f[1] += a.y; f[2] += a.z; f[3] += a.w;
        f[4] += b.x; f[5] += b.y; f[6] += b.z; f[7] += b.w;
    }
#pragma unroll
    for (int j = 0; j < 8; ++j) sred[t * 9 + j] = f[j];

    if (t < 128) {
        int d2 = t & 31;
        int sg = t >> 5;
        float s = 0.f;
#pragma unroll
        for (int i = 0; i < 8; ++i)
            s += g_ksum_part[(br * 32 + sg * 8 + i) * 128 + h * 32 + d2];
        skred[t] = s;
    }
    __syncthreads();

    if (t < 128) {
        float fo[8];
#pragma unroll
        for (int j = 0; j < 8; ++j)
            fo[j] = (sred[(t * 4 + 0) * 9 + j] + sred[(t * 4 + 1) * 9 + j]) +
                    (sred[(t * 4 + 2) * 9 + j] + sred[(t * 4 + 3) * 9 + j]);
        uint4 hi, lo;
        cvt8(fo, hi, lo);
        int idx = h * 128 + t;
        g_ktvimg[(long long)br * 1024 + idx] = hi;
        g_ktvimg[(long long)br * 1024 + 512 + idx] = lo;
    } else if (t < 160) {
        int d2 = t - 128;
        g_ksum_final[blk * 32 + d2] =
            (skred[d2] + skred[32 + d2]) + (skred[64 + d2] + skred[96 + d2]);
    }
}

// ---------------------------------------------------------------------------
// Kernel 3: q projection + t + output projection, all fused.
// ---------------------------------------------------------------------------
__global__ __launch_bounds__(256, 2)
void tout_kernel(const float* __restrict__ X, const float* __restrict__ bq,
                 const float* __restrict__ bo, float* __restrict__ out)
{
    extern __shared__ char smem[];
    const u32 sb = (u32)__cvta_generic_to_shared(smem);

    const int tid = threadIdx.x;
    const int lane = tid & 31;
    const int w = tid >> 5;
    const long long tile = blockIdx.x;
    const long long m0 = tile * 64;
    const int br = (int)(tile >> 5);

    // ---- Phase 1: load X into A images ----
    load_x_images(smem, X + m0 * EE);

    const int wr0 = (w & 1) * 32;
    const int wc0 = (w >> 1) * 32;
    const int hh = w >> 1;
    const int quad = lane >> 3;
    const int l7 = lane & 7;
    const int arow0 = wr0 + l7 + (quad & 1) * 8;
    const int arow1 = arow0 + 16;
    const int axor0 = arow0 & 7;
    const int axor1 = arow1 & 7;
    const int ac_off = quad >> 1;
    const int krow_base = l7 + (quad & 1) * 8;
    const int bxor = krow_base & 7;
    const int g = lane >> 2;
    const int t2 = lane & 3;

    // ---- Phase 2: q = X @ Wq (two-pass hi/lo) ----
    float acc[2][4][4];
#pragma unroll
    for (int ii = 0; ii < 2; ++ii)
#pragma unroll
        for (int jj = 0; jj < 4; ++jj)
#pragma unroll
            for (int kk = 0; kk < 4; ++kk) acc[ii][jj][kk] = 0.f;
    proj_mma(smem, sb, g_wimg + 0 * 4096, acc);   // Wq

    __syncthreads();   // all X ldsm done; W slot free

    // ---- Phase 3: copy KtV images into W region; q epilogue (elu, Z, image) ----
    {
        const uint4* src = g_ktvimg + (long long)br * 1024;
#pragma unroll
        for (int it = 0; it < 2; ++it) {
            int i = tid + it * 256;
            int h = i >> 7;
            int d = (i >> 2) & 31;
            int cc = i & 3;
            int off = (h * 32 + d) * 256 + (((h * 4 + cc) ^ (d & 7)) << 4);
            *(uint4*)(smem + SOFF_WHI2 + off) = src[i];
            *(uint4*)(smem + SOFF_WLO2 + off) = src[512 + i];
        }
    }
    float zr[2][2];
    {
        float ks[4][2];
#pragma unroll
        for (int nt = 0; nt < 4; ++nt) {
            float2 kk = *(const float2*)(g_ksum_final + br * 128 + wc0 + nt * 8 + t2 * 2);
            ks[nt][0] = kk.x;
            ks[nt][1] = kk.y;
        }
#pragma unroll
        for (int mt = 0; mt < 2; ++mt) {
            int r0 = wr0 + mt * 16 + g;
            int r1 = r0 + 8;
            float d0 = 0.f, d1 = 0.f;
#pragma unroll
            for (int nt = 0; nt < 4; ++nt) {
                int col = wc0 + nt * 8 + t2 * 2;
                float2 bb = *(const float2*)(bq + col);
                float v0 = elu1(acc[mt][nt][0] + bb.x);
                float v1 = elu1(acc[mt][nt][1] + bb.y);
                float v2 = elu1(acc[mt][nt][2] + bb.x);
                float v3 = elu1(acc[mt][nt][3] + bb.y);
                d0 = fmaf(v0, ks[nt][0], fmaf(v1, ks[nt][1], d0));
                d1 = fmaf(v2, ks[nt][0], fmaf(v3, ks[nt][1], d1));
                int ch = col >> 3;
                int ib = (col & 7) * 2;
                u32 hi0, lo0, hi1, lo1;
                cvt2(v0, v1, hi0, lo0);
                cvt2(v2, v3, hi1, lo1);
                int off0 = r0 * 256 + ((ch ^ (r0 & 7)) << 4) + ib;
                int off1 = r1 * 256 + ((ch ^ (r1 & 7)) << 4) + ib;
                *(u32*)(smem + SOFF_AHI + off0) = hi0;
                *(u32*)(smem + SOFF_ALO + off0) = lo0;
                *(u32*)(smem + SOFF_AHI + off1) = hi1;
                *(u32*)(smem + SOFF_ALO + off1) = lo1;
            }
            d0 += __shfl_xor_sync(0xffffffffu, d0, 1);
            d0 += __shfl_xor_sync(0xffffffffu, d0, 2);
            d1 += __shfl_xor_sync(0xffffffffu, d1, 1);
            d1 += __shfl_xor_sync(0xffffffffu, d1, 2);
            zr[mt][0] = 1.0f / (d0 + 1e-6f);
            zr[mt][1] = 1.0f / (d1 + 1e-6f);
        }
    }
    __syncthreads();   // q images + KtV images visible

    // ---- Phase 4: t = q @ KtV (per-head K=32), Z-scale, overwrite A in place ----
    {
#pragma unroll
        for (int ii = 0; ii < 2; ++ii)
#pragma unroll
            for (int jj = 0; jj < 4; ++jj)
#pragma unroll
                for (int kk = 0; kk < 4; ++kk) acc[ii][jj][kk] = 0.f;

#pragma unroll
        for (int ks = 0; ks < 2; ++ks) {
            u32 ah0[4], ah1[4], al0[4], al1[4];
            {
                int chA = hh * 4 + ks * 2 + ac_off;
                int offA0 = arow0 * 256 + ((chA ^ axor0) << 4);
                int offA1 = arow1 * 256 + ((chA ^ axor1) << 4);
                ldsm4(sb + SOFF_AHI + offA0, ah0[0], ah0[1], ah0[2], ah0[3]);
                ldsm4(sb + SOFF_ALO + offA0, al0[0], al0[1], al0[2], al0[3]);
                ldsm4(sb + SOFF_AHI + offA1, ah1[0], ah1[1], ah1[2], ah1[3]);
                ldsm4(sb + SOFF_ALO + offA1, al1[0], al1[1], al1[2], al1[3]);
            }
#pragma unroll
            for (int p = 0; p < 2; ++p) {
                int chB = hh * 4 + p * 2 + (quad >> 1);
                int brow = hh * 32 + ks * 16 + krow_base;
                int offB = brow * 256 + ((chB ^ bxor) << 4);
                u32 wb0, wb1, wb2, wb3;
                ldsm4t(sb + SOFF_WHI2 + offB, wb0, wb1, wb2, wb3);
                mma_bf16(acc[0][2 * p],     ah0, wb0, wb1);
                mma_bf16(acc[0][2 * p + 1], ah0, wb2, wb3);
                mma_bf16(acc[1][2 * p],     ah1, wb0, wb1);
                mma_bf16(acc[1][2 * p + 1], ah1, wb2, wb3);
                mma_bf16(acc[0][2 * p],     al0, wb0, wb1);
                mma_bf16(acc[0][2 * p + 1], al0, wb2, wb3);
                mma_bf16(acc[1][2 * p],     al1, wb0, wb1);
                mma_bf16(acc[1][2 * p + 1], al1, wb2, wb3);
                ldsm4t(sb + SOFF_WLO2 + offB, wb0, wb1, wb2, wb3);
                mma_bf16(acc[0][2 * p],     ah0, wb0, wb1);
                mma_bf16(acc[0][2 * p + 1], ah0, wb2, wb3);
                mma_bf16(acc[1][2 * p],     ah1, wb0, wb1);
                mma_bf16(acc[1][2 * p + 1], ah1, wb2, wb3);
            }
        }

        // Z-scale + write t back into the A image (warp-local chunks; no sync)
#pragma unroll
        for (int mt = 0; mt < 2; ++mt) {
            int r0 = wr0 + mt * 16 + g;
            int r1 = r0 + 8;
            float z0 = zr[mt][0];
            float z1 = zr[mt][1];
#pragma unroll
            for (int nt = 0; nt < 4; ++nt) {
                int col = wc0 + nt * 8 + t2 * 2;
                int ch = col >> 3;
                int ib = (col & 7) * 2;
                u32 hi0, lo0, hi1, lo1;
                cvt2(acc[mt][nt][0] * z0, acc[mt][nt][1] * z0, hi0, lo0);
                cvt2(acc[mt][nt][2] * z1, acc[mt][nt][3] * z1, hi1, lo1);
                int off0 = r0 * 256 + ((ch ^ (r0 & 7)) << 4) + ib;
                int off1 = r1 * 256 + ((ch ^ (r1 & 7)) << 4) + ib;
                *(u32*)(smem + SOFF_AHI + off0) = hi0;
                *(u32*)(smem + SOFF_ALO + off0) = lo0;
                *(u32*)(smem + SOFF_AHI + off1) = hi1;
                *(u32*)(smem + SOFF_ALO + off1) = lo1;
            }
        }
    }
    __syncthreads();   // t writes visible; KtV reads done

    // ---- Phase 5: copy Wo images over KtV region ----
    {
        const uint4* wsrc = g_wimg + 3 * 4096;
#pragma unroll
        for (int it = 0; it < 8; ++it) {
            int i = tid + it * 256;
            *(uint4*)(smem + SOFF_WHI2 + i * 16) = wsrc[i];
            *(uint4*)(smem + SOFF_WLO2 + i * 16) = wsrc[2048 + i];
        }
    }
    __syncthreads();

    // ---- Phase 6: out = t @ Wo + bo (K=128) ----
#pragma unroll
    for (int ii = 0; ii < 2; ++ii)
#pragma unroll
        for (int jj = 0; jj < 4; ++jj)
#pragma unroll
            for (int kk = 0; kk < 4; ++kk) acc[ii][jj][kk] = 0.f;

#pragma unroll 1
    for (int ks = 0; ks < 8; ++ks) {
        u32 ah0[4], ah1[4], al0[4], al1[4];
        {
            int offA0 = arow0 * 256 + (((ks * 2 + ac_off) ^ axor0) << 4);
            int offA1 = arow1 * 256 + (((ks * 2 + ac_off) ^ axor1) << 4);
            ldsm4(sb + SOFF_AHI + offA0, ah0[0], ah0[1], ah0[2], ah0[3]);
            ldsm4(sb + SOFF_ALO + offA0, al0[0], al0[1], al0[2], al0[3]);
            ldsm4(sb + SOFF_AHI + offA1, ah1[0], ah1[1], ah1[2], ah1[3]);
            ldsm4(sb + SOFF_ALO + offA1, al1[0], al1[1], al1[2], al1[3]);
        }
#pragma unroll
        for (int p = 0; p < 2; ++p) {
            int chB = (wc0 >> 3) + p * 2 + (quad >> 1);
            int offB = (ks * 16 + krow_base) * 256 + ((chB ^ bxor) << 4);
            u32 wb0, wb1, wb2, wb3;
            ldsm4t(sb + SOFF_WHI2 + offB, wb0, wb1, wb2, wb3);
            mma_bf16(acc[0][2 * p],     ah0, wb0, wb1);
            mma_bf16(acc[0][2 * p + 1], ah0, wb2, wb3);
            mma_bf16(acc[1][2 * p],     ah1, wb0, wb1);
            mma_bf16(acc[1][2 * p + 1], ah1, wb2, wb3);
            mma_bf16(acc[0][2 * p],     al0, wb0, wb1);
            mma_bf16(acc[0][2 * p + 1], al0, wb2, wb3);
            mma_bf16(acc[1][2 * p],     al1, wb0, wb1);
            mma_bf16(acc[1][2 * p + 1], al1, wb2, wb3);
            ldsm4t(sb + SOFF_WLO2 + offB, wb0, wb1, wb2, wb3);
            mma_bf16(acc[0][2 * p],     ah0, wb0, wb1);
            mma_bf16(acc[0][2 * p + 1], ah0, wb2, wb3);
            mma_bf16(acc[1][2 * p],     ah1, wb0, wb1);
            mma_bf16(acc[1][2 * p + 1], ah1, wb2, wb3);
        }
    }

#pragma unroll
    for (int mt = 0; mt < 2; ++mt) {
#pragma unroll
        for (int nt = 0; nt < 4; ++nt) {
            int col = wc0 + nt * 8 + t2 * 2;
            float2 bb = *(const float2*)(bo + col);
            long long r0g = m0 + wr0 + mt * 16 + g;
            float v0 = acc[mt][nt][0] + bb.x;
            float v1 = acc[mt][nt][1] + bb.y;
            float v2 = acc[mt][nt][2] + bb.x;
            float v3 = acc[mt][nt][3] + bb.y;
            *(float2*)(out + r0g * EE + col)       = make_float2(v0, v1);
            *(float2*)(out + (r0g + 8) * EE + col) = make_float2(v2, v3);
        }
    }
}

// ---------------------------------------------------------------------------
extern "C" void kernel_launch(void* const* d_in, const int* in_sizes, int n_in,
                              void* d_out, int out_size)
{
    const float* X  = (const float*)d_in[0];
    const float* Wq = (const float*)d_in[1];
    const float* bq = (const float*)d_in[2];
    const float* Wk = (const float*)d_in[3];
    const float* bk = (const float*)d_in[4];
    const float* Wv = (const float*)d_in[5];
    const float* bv = (const float*)d_in[6];
    const float* Wo = (const float*)d_in[7];
    const float* bo = (const float*)d_in[8];
    float* out = (float*)d_out;

    cudaFuncSetAttribute(fused_kv_ktv_kernel, cudaFuncAttributeMaxDynamicSharedMemorySize, SMEM_FUSED);
    cudaFuncSetAttribute(tout_kernel, cudaFuncAttributeMaxDynamicSharedMemorySize, SMEM_TOUT);

    prep_w_kernel<<<4, 256>>>(Wq, Wk, Wv, Wo);
    fused_kv_ktv_kernel<<<NTILES, 256, SMEM_FUSED>>>(X, bk, bv);
    ktv_reduce_kernel<<<NKV, 512>>>();
    tout_kernel<<<NTILES, 256, SMEM_TOUT>>>(X, bq, bo, out);
}